// round 3
// baseline (speedup 1.0000x reference)
#include <cuda_runtime.h>
#include <math.h>

#define NN 20000
#define EE 320000
#define EH 160000
#define EPSV 1e-6f

// ---------------- scratch (static device globals; no allocs) ----------------
__device__ float g_h1[NN * 64];        // hidden of input MLP / hidden of output MLP
__device__ float g_h[NN * 128];        // h, then h3 updated in place
__device__ float g_P[NN * 128];        // [A | B] per node
__device__ float g_Wab[128 * 128];     // packed w_map1 for A|B gemm
__device__ float g_Weff0[128 * 128];   // W1_0^T (x) W2_0 kron weight
__device__ float g_Weff1[128 * 128];   // W1_1^T (x) W2_1 kron weight
__device__ float g_maps[EE * 4];       // edge restriction maps (2x2)
__device__ float g_Dinv[NN * 4];       // D^{-1/2} blocks (2x2 symmetric)
__device__ float g_diagn[NN * 4];      // normalized diag blocks
__device__ float g_offn[EE * 4];       // normalized off-diag blocks
__device__ float g_Ht[NN * 128];       // W1^T (h3 W2^T) per node
__device__ int g_deg[NN];
__device__ int g_cursor[NN];
__device__ int g_rowptr[NN + 1];
__device__ int g_adj[EE];

__device__ __forceinline__ float eluf(float v) {
    return v > 0.f ? v : (expf(v) - 1.f);
}

// ---------------- tiled fp32 GEMM: C = act(A[M,K] @ W[N,K]^T + bias) ----------------
// BM x BN tile, BK=8, 256 threads, TM x TN register tile, register-prefetch pipeline.
template <int BM, int BN, int TM, int TN, bool RELU>
__global__ void __launch_bounds__(256) gemm2(const float* __restrict__ A,
                                             const float* __restrict__ W,
                                             const float* __restrict__ bias,
                                             float* __restrict__ C,
                                             int M, int N, int K) {
    __shared__ float As[8][BM];
    __shared__ float Bs[8][BN];

    const int tid = threadIdx.x;
    const int bm = blockIdx.y * BM;
    const int bn = blockIdx.x * BN;

    // thread tile coords
    const int tx = tid % (BN / TN);
    const int ty = tid / (BN / TN);
    const int m0 = ty * TM;
    const int n0 = tx * TN;

    // A loader: BM*8/256 = 4 elems -> one float4 along K
    const int a_m = tid >> 1;
    const int a_k = (tid & 1) * 4;
    const bool a_ok = (bm + a_m) < M;
    const float* Ag = A + (size_t)(bm + a_m) * K + a_k;

    // B loader
    const int b_n = tid >> 1;
    const int b_k = (tid & 1) * 4;
    const bool b_active = (BN == 128) ? true : (tid < 128);
    const bool b_ok = b_active && (bn + b_n) < N;
    const float* Wg = W + (size_t)(bn + b_n) * K + b_k;

    float acc[TM][TN];
#pragma unroll
    for (int i = 0; i < TM; i++)
#pragma unroll
        for (int j = 0; j < TN; j++) acc[i][j] = 0.f;

    float4 av = a_ok ? *(const float4*)Ag : make_float4(0.f, 0.f, 0.f, 0.f);
    float4 bv = b_ok ? *(const float4*)Wg : make_float4(0.f, 0.f, 0.f, 0.f);

    for (int k0 = 0; k0 < K; k0 += 8) {
        // store current stage
        As[a_k + 0][a_m] = av.x; As[a_k + 1][a_m] = av.y;
        As[a_k + 2][a_m] = av.z; As[a_k + 3][a_m] = av.w;
        if (b_active) {
            Bs[b_k + 0][b_n] = bv.x; Bs[b_k + 1][b_n] = bv.y;
            Bs[b_k + 2][b_n] = bv.z; Bs[b_k + 3][b_n] = bv.w;
        }
        __syncthreads();

        // prefetch next stage into registers (hidden behind compute)
        if (k0 + 8 < K) {
            av = a_ok ? *(const float4*)(Ag + k0 + 8) : make_float4(0.f, 0.f, 0.f, 0.f);
            bv = b_ok ? *(const float4*)(Wg + k0 + 8) : make_float4(0.f, 0.f, 0.f, 0.f);
        }

#pragma unroll
        for (int kk = 0; kk < 8; kk++) {
            float a[TM], b[TN];
#pragma unroll
            for (int i4 = 0; i4 < TM / 4; i4++) {
                float4 t = *(const float4*)(&As[kk][m0 + i4 * 4]);
                a[i4 * 4 + 0] = t.x; a[i4 * 4 + 1] = t.y;
                a[i4 * 4 + 2] = t.z; a[i4 * 4 + 3] = t.w;
            }
#pragma unroll
            for (int j4 = 0; j4 < TN / 4; j4++) {
                float4 t = *(const float4*)(&Bs[kk][n0 + j4 * 4]);
                b[j4 * 4 + 0] = t.x; b[j4 * 4 + 1] = t.y;
                b[j4 * 4 + 2] = t.z; b[j4 * 4 + 3] = t.w;
            }
#pragma unroll
            for (int i = 0; i < TM; i++)
#pragma unroll
                for (int j = 0; j < TN; j++) acc[i][j] += a[i] * b[j];
        }
        __syncthreads();
    }

    // epilogue: float4 stores (all our Ns are multiples of 4)
#pragma unroll
    for (int i = 0; i < TM; i++) {
        int m = bm + m0 + i;
        if (m >= M) continue;
#pragma unroll
        for (int j4 = 0; j4 < TN / 4; j4++) {
            int n = bn + n0 + j4 * 4;
            if (n + 3 < N || n < N) {
                if (n + 3 < N) {
                    float4 v;
                    v.x = acc[i][j4 * 4 + 0] + (bias ? bias[n + 0] : 0.f);
                    v.y = acc[i][j4 * 4 + 1] + (bias ? bias[n + 1] : 0.f);
                    v.z = acc[i][j4 * 4 + 2] + (bias ? bias[n + 2] : 0.f);
                    v.w = acc[i][j4 * 4 + 3] + (bias ? bias[n + 3] : 0.f);
                    if (RELU) {
                        v.x = fmaxf(v.x, 0.f); v.y = fmaxf(v.y, 0.f);
                        v.z = fmaxf(v.z, 0.f); v.w = fmaxf(v.w, 0.f);
                    }
                    *(float4*)(C + (size_t)m * N + n) = v;
                } else {
                    for (int j = 0; j < 4 && n + j < N; j++) {
                        float v = acc[i][j4 * 4 + j] + (bias ? bias[n + j] : 0.f);
                        if (RELU) v = fmaxf(v, 0.f);
                        C[(size_t)m * N + n + j] = v;
                    }
                }
            }
        }
    }
}

// ---------------- prep: pack Wab, build Weff kron weights, zero counters ----------------
__global__ void prep_k(const float* __restrict__ w_map1,
                       const float* __restrict__ W1_0, const float* __restrict__ W2_0,
                       const float* __restrict__ W1_1, const float* __restrict__ W2_1) {
    int i = blockIdx.x * blockDim.x + threadIdx.x;
    if (i < 128 * 128) {
        int j = i >> 7, k = i & 127;
        g_Wab[i] = (j < 64) ? w_map1[j * 256 + k] : w_map1[(j - 64) * 256 + 128 + k];
        // Weff[(ii*64+g)][(jj*64+f)] = W1[jj][ii] * W2[g][f]
        int r = i >> 7, c = i & 127;
        int ii = r >> 6, g = r & 63;
        int jj = c >> 6, f = c & 63;
        g_Weff0[i] = W1_0[jj * 2 + ii] * W2_0[g * 64 + f];
        g_Weff1[i] = W1_1[jj * 2 + ii] * W2_1[g * 64 + f];
    }
    if (i < NN) {
        g_deg[i] = 0;
        g_cursor[i] = 0;
    }
}

// ---------------- CSR build ----------------
__global__ void hist_k(const int* __restrict__ src) {
    int e = blockIdx.x * blockDim.x + threadIdx.x;
    if (e < EE) atomicAdd(&g_deg[src[e]], 1);
}

__global__ void __launch_bounds__(1024) scan_k() {
    __shared__ int wsum[32];
    __shared__ int carry;
    int t = threadIdx.x, l = t & 31, w = t >> 5;
    if (t == 0) { carry = 0; g_rowptr[0] = 0; }
    __syncthreads();
    for (int base = 0; base < NN; base += 1024) {
        int v = (base + t < NN) ? g_deg[base + t] : 0;
        int x = v;
#pragma unroll
        for (int o = 1; o < 32; o <<= 1) {
            int y = __shfl_up_sync(0xFFFFFFFFu, x, o);
            if (l >= o) x += y;
        }
        if (l == 31) wsum[w] = x;
        __syncthreads();
        if (w == 0) {
            int y = wsum[l];
#pragma unroll
            for (int o = 1; o < 32; o <<= 1) {
                int z = __shfl_up_sync(0xFFFFFFFFu, y, o);
                if (l >= o) y += z;
            }
            wsum[l] = y;
        }
        __syncthreads();
        int off = carry + (w > 0 ? wsum[w - 1] : 0);
        if (base + t < NN) g_rowptr[base + t + 1] = off + x;
        __syncthreads();
        if (t == 0) carry += wsum[31];
        __syncthreads();
    }
}

__global__ void scatter_k(const int* __restrict__ src) {
    int e = blockIdx.x * blockDim.x + threadIdx.x;
    if (e < EE) {
        int s = src[e];
        int p = atomicAdd(&g_cursor[s], 1);
        g_adj[g_rowptr[s] + p] = e;
    }
}

// ---------------- edge restriction maps (warp per edge) ----------------
__global__ void __launch_bounds__(256) edge_maps_k(const int* __restrict__ src,
                                                   const int* __restrict__ dst,
                                                   const float* __restrict__ b_map1,
                                                   const float* __restrict__ w_map2,
                                                   const float* __restrict__ b_map2) {
    int w = threadIdx.x >> 5, l = threadIdx.x & 31;
    int e = blockIdx.x * 8 + w;
    if (e >= EE) return;
    int s = src[e], d = dst[e];
    float h0 = g_P[s * 128 + l] + g_P[d * 128 + 64 + l] + b_map1[l];
    float h1 = g_P[s * 128 + 32 + l] + g_P[d * 128 + 96 + l] + b_map1[32 + l];
    h0 = fmaxf(h0, 0.f);
    h1 = fmaxf(h1, 0.f);
    float p0 = h0 * w_map2[l] + h1 * w_map2[32 + l];
    float p1 = h0 * w_map2[64 + l] + h1 * w_map2[96 + l];
    float p2 = h0 * w_map2[128 + l] + h1 * w_map2[160 + l];
    float p3 = h0 * w_map2[192 + l] + h1 * w_map2[224 + l];
#pragma unroll
    for (int o = 16; o > 0; o >>= 1) {
        p0 += __shfl_xor_sync(0xFFFFFFFFu, p0, o);
        p1 += __shfl_xor_sync(0xFFFFFFFFu, p1, o);
        p2 += __shfl_xor_sync(0xFFFFFFFFu, p2, o);
        p3 += __shfl_xor_sync(0xFFFFFFFFu, p3, o);
    }
    if (l == 0) {
        ((float4*)g_maps)[e] =
            make_float4(p0 + b_map2[0], p1 + b_map2[1], p2 + b_map2[2], p3 + b_map2[3]);
    }
}

// ---------------- per-node: diag = segsum(F^T F), Dinv, diag_n ----------------
__global__ void node_diag_k() {
    int n = blockIdx.x * blockDim.x + threadIdx.x;
    if (n >= NN) return;
    float f00 = 0.f, f01 = 0.f, f11 = 0.f;
    int beg = g_rowptr[n], end = g_rowptr[n + 1];
    const float4* maps4 = (const float4*)g_maps;
    for (int i = beg; i < end; i++) {
        float4 m = maps4[g_adj[i]];
        f00 += m.x * m.x + m.z * m.z;
        f01 += m.x * m.y + m.z * m.w;
        f11 += m.y * m.y + m.w * m.w;
    }
    // analytic D^{-1/2} of symmetric 2x2 (spectral function: basis independent)
    float t = 0.5f * (f00 + f11);
    float dd = 0.5f * (f00 - f11);
    float rad = sqrtf(dd * dd + f01 * f01);
    float l1 = t - rad, l2 = t + rad;
    float s1 = rsqrtf(fmaxf(l1, EPSV));
    float s2 = rsqrtf(fmaxf(l2, EPSV));
    float c0 = 0.5f * (s1 + s2);
    float c1 = (rad > 1e-20f) ? (s2 - s1) / (2.f * rad) : 0.f;
    float D00 = c0 + c1 * dd;
    float D01 = c1 * f01;
    float D11 = c0 - c1 * dd;
    // diag_n = D M D
    float g00 = f00 * D00 + f01 * D01, g01 = f00 * D01 + f01 * D11;
    float g10 = f01 * D00 + f11 * D01, g11 = f01 * D01 + f11 * D11;
    float dn00 = D00 * g00 + D01 * g10, dn01 = D00 * g01 + D01 * g11;
    float dn10 = D01 * g00 + D11 * g10, dn11 = D01 * g01 + D11 * g11;
    ((float4*)g_Dinv)[n] = make_float4(D00, D01, D01, D11);
    ((float4*)g_diagn)[n] = make_float4(dn00, dn01, dn10, dn11);
}

// ---------------- per-edge normalized off-diagonal blocks ----------------
__global__ void edge_offn_k(const int* __restrict__ src, const int* __restrict__ dst) {
    int e = blockIdx.x * blockDim.x + threadIdx.x;
    if (e >= EE) return;
    int r = (e < EH) ? e + EH : e - EH;
    const float4* maps4 = (const float4*)g_maps;
    float4 me = maps4[e];
    float4 mr = maps4[r];
    float o00 = -(me.x * mr.x + me.z * mr.z);
    float o01 = -(me.x * mr.y + me.z * mr.w);
    float o10 = -(me.y * mr.x + me.w * mr.z);
    float o11 = -(me.y * mr.y + me.w * mr.w);
    float4 Ds = ((const float4*)g_Dinv)[src[e]];
    float4 Dd = ((const float4*)g_Dinv)[dst[e]];
    float t00 = Ds.x * o00 + Ds.y * o10, t01 = Ds.x * o01 + Ds.y * o11;
    float t10 = Ds.z * o00 + Ds.w * o10, t11 = Ds.z * o01 + Ds.w * o11;
    float n00 = t00 * Dd.x + t01 * Dd.z, n01 = t00 * Dd.y + t01 * Dd.w;
    float n10 = t10 * Dd.x + t11 * Dd.z, n11 = t10 * Dd.y + t11 * Dd.w;
    ((float4*)g_offn)[e] = make_float4(n00, n01, n10, n11);
}

// ---------------- gather-based sheaf aggregation + elu update (warp per node) -------------
__global__ void __launch_bounds__(256) aggregate_k(const int* __restrict__ dst) {
    int w = threadIdx.x >> 5, l = threadIdx.x & 31;
    int n = blockIdx.x * 8 + w;
    if (n >= NN) return;
    const float* Hn = g_Ht + (size_t)n * 128;
    float ht0a = Hn[l], ht0b = Hn[32 + l], ht1a = Hn[64 + l], ht1b = Hn[96 + l];
    float4 dn = ((const float4*)g_diagn)[n];
    float a0a = dn.x * ht0a + dn.y * ht1a;
    float a0b = dn.x * ht0b + dn.y * ht1b;
    float a1a = dn.z * ht0a + dn.w * ht1a;
    float a1b = dn.z * ht0b + dn.w * ht1b;
    int beg = g_rowptr[n], end = g_rowptr[n + 1];
    const float4* offn4 = (const float4*)g_offn;
    for (int i = beg; i < end; i++) {
        int e = g_adj[i];
        int dd = dst[e];
        float4 o = offn4[e];
        const float* H = g_Ht + (size_t)dd * 128;
        float x0a = H[l], x0b = H[32 + l], x1a = H[64 + l], x1b = H[96 + l];
        a0a += o.x * x0a + o.y * x1a;
        a0b += o.x * x0b + o.y * x1b;
        a1a += o.z * x0a + o.w * x1a;
        a1b += o.z * x0b + o.w * x1b;
    }
    float* h3 = g_h + (size_t)n * 128;
    h3[l] -= eluf(a0a);
    h3[32 + l] -= eluf(a0b);
    h3[64 + l] -= eluf(a1a);
    h3[96 + l] -= eluf(a1b);
}

// ---------------- host ----------------
extern "C" void kernel_launch(void* const* d_in, const int* in_sizes, int n_in,
                              void* d_out, int out_size) {
    (void)in_sizes; (void)n_in; (void)out_size;
    const float* x = (const float*)d_in[0];
    const int* ei = (const int*)d_in[1];
    const int* src = ei;
    const int* dst = ei + EE;
    const float* w_in1 = (const float*)d_in[2];
    const float* b_in1 = (const float*)d_in[3];
    const float* w_in2 = (const float*)d_in[4];
    const float* b_in2 = (const float*)d_in[5];
    const float* w_map1 = (const float*)d_in[6];
    const float* b_map1 = (const float*)d_in[7];
    const float* w_map2 = (const float*)d_in[8];
    const float* b_map2 = (const float*)d_in[9];
    const float* w_out1 = (const float*)d_in[10];
    const float* b_out1 = (const float*)d_in[11];
    const float* w_out2 = (const float*)d_in[12];
    const float* b_out2 = (const float*)d_in[13];
    const float* W1_0 = (const float*)d_in[14];
    const float* W2_0 = (const float*)d_in[15];
    const float* W1_1 = (const float*)d_in[16];
    const float* W2_1 = (const float*)d_in[17];
    float* out = (float*)d_out;

    void *p_h1, *p_h, *p_P, *p_Wab, *p_We0, *p_We1, *p_Ht;
    cudaGetSymbolAddress(&p_h1, g_h1);
    cudaGetSymbolAddress(&p_h, g_h);
    cudaGetSymbolAddress(&p_P, g_P);
    cudaGetSymbolAddress(&p_Wab, g_Wab);
    cudaGetSymbolAddress(&p_We0, g_Weff0);
    cudaGetSymbolAddress(&p_We1, g_Weff1);
    cudaGetSymbolAddress(&p_Ht, g_Ht);

    const int MB = (NN + 127) / 128;  // 157

    // prep: pack Wab, build Weff kron weights, zero counters
    prep_k<<<79, 256>>>(w_map1, W1_0, W2_0, W1_1, W2_1);

    // input MLP
    gemm2<128, 64, 8, 4, true><<<dim3(1, MB), 256>>>(x, w_in1, b_in1, (float*)p_h1,
                                                     NN, 64, 512);
    gemm2<128, 128, 8, 8, false><<<dim3(1, MB), 256>>>((const float*)p_h1, w_in2, b_in2,
                                                       (float*)p_h, NN, 128, 64);
    // per-node A|B partials for the edge MLP
    gemm2<128, 128, 8, 8, false><<<dim3(1, MB), 256>>>((const float*)p_h,
                                                       (const float*)p_Wab, nullptr,
                                                       (float*)p_P, NN, 128, 128);

    // CSR by src
    hist_k<<<1250, 256>>>(src);
    scan_k<<<1, 1024>>>();
    scatter_k<<<1250, 256>>>(src);

    // edge maps, diag blocks, off blocks
    edge_maps_k<<<EE / 8, 256>>>(src, dst, b_map1, w_map2, b_map2);
    node_diag_k<<<79, 256>>>();
    edge_offn_k<<<1250, 256>>>(src, dst);

    // two sheaf-diffusion layers: Ht = h3 @ Weff^T (fused W1/W2), then aggregate
    const float* We[2] = {(const float*)p_We0, (const float*)p_We1};
    for (int layer = 0; layer < 2; layer++) {
        gemm2<128, 128, 8, 8, false><<<dim3(1, MB), 256>>>((const float*)p_h, We[layer],
                                                           nullptr, (float*)p_Ht,
                                                           NN, 128, 128);
        aggregate_k<<<2500, 256>>>(dst);
    }

    // output MLP
    gemm2<128, 64, 8, 4, true><<<dim3(1, MB), 256>>>((const float*)p_h, w_out1, b_out1,
                                                     (float*)p_h1, NN, 64, 128);
    gemm2<128, 64, 8, 4, false><<<dim3(1, MB), 256>>>((const float*)p_h1, w_out2, b_out2,
                                                      out, NN, 40, 64);
}

// round 4
// speedup vs baseline: 1.4462x; 1.4462x over previous
#include <cuda_runtime.h>
#include <cuda_bf16.h>
#include <math.h>
#include <stdint.h>

#define NN 20000
#define EE 320000
#define EH 160000
#define EPSV 1e-6f

// ---------------- scratch (static device globals; no allocs) ----------------
__device__ float g_h1[NN * 64];        // hidden of input MLP / hidden of output MLP
__device__ float g_h[NN * 128];        // h, then h3 updated in place
__device__ float g_P[NN * 128];        // [A | B] per node
__device__ float g_Wab[128 * 128];     // packed w_map1 for A|B gemm
__device__ float g_Weff0[128 * 128];   // W1_0^T (x) W2_0 kron weight
__device__ float g_Weff1[128 * 128];   // W1_1^T (x) W2_1 kron weight
__device__ float g_maps[EE * 4];       // edge restriction maps (2x2)
__device__ float g_Dinv[NN * 4];       // D^{-1/2} blocks (2x2 symmetric)
__device__ float g_diagn[NN * 4];      // normalized diag blocks
__device__ float g_offn[EE * 4];       // normalized off-diag blocks
__device__ float g_Ht[NN * 128];       // W1^T (h3 W2^T) per node
__device__ int g_deg[NN];
__device__ int g_cursor[NN];
__device__ int g_rowptr[NN + 1];
__device__ int g_adj[EE];

__device__ __forceinline__ float eluf(float v) {
    return v > 0.f ? v : (expf(v) - 1.f);
}

__device__ __forceinline__ uint32_t packbf(__nv_bfloat16 a, __nv_bfloat16 b) {
    __nv_bfloat162 t = __halves2bfloat162(a, b);  // low = a
    return *reinterpret_cast<uint32_t*>(&t);
}

#define MMA16816(c, a, b0_, b1_)                                             \
    asm volatile(                                                            \
        "mma.sync.aligned.m16n8k16.row.col.f32.bf16.bf16.f32 "               \
        "{%0,%1,%2,%3}, {%4,%5,%6,%7}, {%8,%9}, {%0,%1,%2,%3};"              \
        : "+f"((c)[0]), "+f"((c)[1]), "+f"((c)[2]), "+f"((c)[3])             \
        : "r"((a)[0]), "r"((a)[1]), "r"((a)[2]), "r"((a)[3]),                \
          "r"(b0_), "r"(b1_))

// ---------------- tensor-core GEMM: C = act(A[M,K] @ W[N,K]^T + bias) ----------------
// bf16 hi/lo split (3 MMA products) -> fp32-equivalent accuracy.
// BM=128, BN in {128,64}, BK=16, 256 threads (8 warps: 4 along M, 2 along N).
template <int BN, bool RELU>
__global__ void __launch_bounds__(256) gemm_mma(const float* __restrict__ A,
                                                const float* __restrict__ W,
                                                const float* __restrict__ bias,
                                                float* __restrict__ C,
                                                int M, int N, int K) {
    constexpr int BM = 128;
    constexpr int WN = BN / 2;     // warp tile cols
    constexpr int NSUB = WN / 8;   // n-subtiles per warp
    constexpr int SW = 12;         // smem 32-bit words per row (8 data + 4 pad)

    __shared__ uint32_t sAh[BM * SW], sAl[BM * SW];
    __shared__ uint32_t sWh[BN * SW], sWl[BN * SW];

    const int tid = threadIdx.x;
    const int lane = tid & 31;
    const int wid = tid >> 5;
    const int warp_m = wid & 3;
    const int warp_n = wid >> 2;
    const int qr = lane >> 2;  // 0..7
    const int qc = lane & 3;   // 0..3

    const int bm = blockIdx.y * BM;
    const int bn = blockIdx.x * BN;

    const int lm = tid >> 2;          // loader row 0..63
    const int lk = (tid & 3) * 4;     // loader k-offset (floats)
    const int wof = lk >> 1;          // word offset within row (lk/2, 2 words per float4... lk halves -> lk/2 words... careful below)

    float acc[2][NSUB][4];
#pragma unroll
    for (int i = 0; i < 2; i++)
#pragma unroll
        for (int j = 0; j < NSUB; j++)
#pragma unroll
            for (int q = 0; q < 4; q++) acc[i][j][q] = 0.f;

    float4 a_reg[2];
    float4 w_reg[BN / 64];

    auto loadA = [&](int k0) {
#pragma unroll
        for (int i = 0; i < 2; i++) {
            int m = bm + lm + i * 64;
            a_reg[i] = (m < M) ? *(const float4*)(A + (size_t)m * K + k0 + lk)
                               : make_float4(0.f, 0.f, 0.f, 0.f);
        }
    };
    auto loadW = [&](int k0) {
#pragma unroll
        for (int i = 0; i < BN / 64; i++) {
            int n = bn + lm + i * 64;
            w_reg[i] = (n < N) ? *(const float4*)(W + (size_t)n * K + k0 + lk)
                               : make_float4(0.f, 0.f, 0.f, 0.f);
        }
    };

    auto storeSplit = [&](uint32_t* hi, uint32_t* lo, int row, float4 v) {
        __nv_bfloat16 h0 = __float2bfloat16(v.x), h1 = __float2bfloat16(v.y);
        __nv_bfloat16 h2 = __float2bfloat16(v.z), h3 = __float2bfloat16(v.w);
        __nv_bfloat16 l0 = __float2bfloat16(v.x - __bfloat162float(h0));
        __nv_bfloat16 l1 = __float2bfloat16(v.y - __bfloat162float(h1));
        __nv_bfloat16 l2 = __float2bfloat16(v.z - __bfloat162float(h2));
        __nv_bfloat16 l3 = __float2bfloat16(v.w - __bfloat162float(h3));
        int w0 = row * SW + wof;  // lk floats -> lk halves -> lk/2 words
        hi[w0 + 0] = packbf(h0, h1);
        hi[w0 + 1] = packbf(h2, h3);
        lo[w0 + 0] = packbf(l0, l1);
        lo[w0 + 1] = packbf(l2, l3);
    };

    loadA(0);
    loadW(0);

    for (int k0 = 0; k0 < K; k0 += 16) {
#pragma unroll
        for (int i = 0; i < 2; i++) storeSplit(sAh, sAl, lm + i * 64, a_reg[i]);
#pragma unroll
        for (int i = 0; i < BN / 64; i++) storeSplit(sWh, sWl, lm + i * 64, w_reg[i]);
        __syncthreads();

        if (k0 + 16 < K) {
            loadA(k0 + 16);
            loadW(k0 + 16);
        }

        // A fragments (hi + lo)
        uint32_t ah[2][4], al[2][4];
#pragma unroll
        for (int ms = 0; ms < 2; ms++) {
            int r = warp_m * 32 + ms * 16 + qr;
            int b0 = r * SW + qc;
            ah[ms][0] = sAh[b0];
            ah[ms][1] = sAh[b0 + 8 * SW];
            ah[ms][2] = sAh[b0 + 4];
            ah[ms][3] = sAh[b0 + 8 * SW + 4];
            al[ms][0] = sAl[b0];
            al[ms][1] = sAl[b0 + 8 * SW];
            al[ms][2] = sAl[b0 + 4];
            al[ms][3] = sAl[b0 + 8 * SW + 4];
        }

#pragma unroll
        for (int ns = 0; ns < NSUB; ns++) {
            int n = warp_n * WN + ns * 8 + qr;
            int b = n * SW + qc;
            uint32_t bh0 = sWh[b], bh1 = sWh[b + 4];
            uint32_t bl0 = sWl[b], bl1 = sWl[b + 4];
#pragma unroll
            for (int ms = 0; ms < 2; ms++) {
                MMA16816(acc[ms][ns], ah[ms], bh0, bh1);
                MMA16816(acc[ms][ns], ah[ms], bl0, bl1);
                MMA16816(acc[ms][ns], al[ms], bh0, bh1);
            }
        }
        __syncthreads();
    }

    // epilogue
#pragma unroll
    for (int ms = 0; ms < 2; ms++) {
#pragma unroll
        for (int ns = 0; ns < NSUB; ns++) {
            int m0 = bm + warp_m * 32 + ms * 16 + qr;
            int n0 = bn + warp_n * WN + ns * 8 + 2 * qc;
            const float* c = acc[ms][ns];
#pragma unroll
            for (int half = 0; half < 2; half++) {
                int m = m0 + half * 8;
                if (m >= M) continue;
                float v0 = c[half * 2 + 0];
                float v1 = c[half * 2 + 1];
                if (n0 + 1 < N) {
                    v0 += bias ? bias[n0] : 0.f;
                    v1 += bias ? bias[n0 + 1] : 0.f;
                    if (RELU) { v0 = fmaxf(v0, 0.f); v1 = fmaxf(v1, 0.f); }
                    float2 st = make_float2(v0, v1);
                    *(float2*)(C + (size_t)m * N + n0) = st;
                } else if (n0 < N) {
                    v0 += bias ? bias[n0] : 0.f;
                    if (RELU) v0 = fmaxf(v0, 0.f);
                    C[(size_t)m * N + n0] = v0;
                }
            }
        }
    }
}

// ---------------- prep: pack Wab, build Weff kron weights, zero counters ----------------
__global__ void prep_k(const float* __restrict__ w_map1,
                       const float* __restrict__ W1_0, const float* __restrict__ W2_0,
                       const float* __restrict__ W1_1, const float* __restrict__ W2_1) {
    int i = blockIdx.x * blockDim.x + threadIdx.x;
    if (i < 128 * 128) {
        int j = i >> 7, k = i & 127;
        g_Wab[i] = (j < 64) ? w_map1[j * 256 + k] : w_map1[(j - 64) * 256 + 128 + k];
        // Weff[(ii*64+g)][(jj*64+f)] = W1[jj][ii] * W2[g][f]
        int r = i >> 7, c = i & 127;
        int ii = r >> 6, g = r & 63;
        int jj = c >> 6, f = c & 63;
        g_Weff0[i] = W1_0[jj * 2 + ii] * W2_0[g * 64 + f];
        g_Weff1[i] = W1_1[jj * 2 + ii] * W2_1[g * 64 + f];
    }
    if (i < NN) {
        g_deg[i] = 0;
        g_cursor[i] = 0;
    }
}

// ---------------- CSR build ----------------
__global__ void hist_k(const int* __restrict__ src) {
    int e = blockIdx.x * blockDim.x + threadIdx.x;
    if (e < EE) atomicAdd(&g_deg[src[e]], 1);
}

__global__ void __launch_bounds__(1024) scan_k() {
    __shared__ int wsum[32];
    __shared__ int carry;
    int t = threadIdx.x, l = t & 31, w = t >> 5;
    if (t == 0) { carry = 0; g_rowptr[0] = 0; }
    __syncthreads();
    for (int base = 0; base < NN; base += 1024) {
        int v = (base + t < NN) ? g_deg[base + t] : 0;
        int x = v;
#pragma unroll
        for (int o = 1; o < 32; o <<= 1) {
            int y = __shfl_up_sync(0xFFFFFFFFu, x, o);
            if (l >= o) x += y;
        }
        if (l == 31) wsum[w] = x;
        __syncthreads();
        if (w == 0) {
            int y = wsum[l];
#pragma unroll
            for (int o = 1; o < 32; o <<= 1) {
                int z = __shfl_up_sync(0xFFFFFFFFu, y, o);
                if (l >= o) y += z;
            }
            wsum[l] = y;
        }
        __syncthreads();
        int off = carry + (w > 0 ? wsum[w - 1] : 0);
        if (base + t < NN) g_rowptr[base + t + 1] = off + x;
        __syncthreads();
        if (t == 0) carry += wsum[31];
        __syncthreads();
    }
}

__global__ void scatter_k(const int* __restrict__ src) {
    int e = blockIdx.x * blockDim.x + threadIdx.x;
    if (e < EE) {
        int s = src[e];
        int p = atomicAdd(&g_cursor[s], 1);
        g_adj[g_rowptr[s] + p] = e;
    }
}

// ---------------- edge restriction maps (warp per edge) ----------------
__global__ void __launch_bounds__(256) edge_maps_k(const int* __restrict__ src,
                                                   const int* __restrict__ dst,
                                                   const float* __restrict__ b_map1,
                                                   const float* __restrict__ w_map2,
                                                   const float* __restrict__ b_map2) {
    int w = threadIdx.x >> 5, l = threadIdx.x & 31;
    int e = blockIdx.x * 8 + w;
    if (e >= EE) return;
    int s = src[e], d = dst[e];
    float h0 = g_P[s * 128 + l] + g_P[d * 128 + 64 + l] + b_map1[l];
    float h1 = g_P[s * 128 + 32 + l] + g_P[d * 128 + 96 + l] + b_map1[32 + l];
    h0 = fmaxf(h0, 0.f);
    h1 = fmaxf(h1, 0.f);
    float p0 = h0 * w_map2[l] + h1 * w_map2[32 + l];
    float p1 = h0 * w_map2[64 + l] + h1 * w_map2[96 + l];
    float p2 = h0 * w_map2[128 + l] + h1 * w_map2[160 + l];
    float p3 = h0 * w_map2[192 + l] + h1 * w_map2[224 + l];
#pragma unroll
    for (int o = 16; o > 0; o >>= 1) {
        p0 += __shfl_xor_sync(0xFFFFFFFFu, p0, o);
        p1 += __shfl_xor_sync(0xFFFFFFFFu, p1, o);
        p2 += __shfl_xor_sync(0xFFFFFFFFu, p2, o);
        p3 += __shfl_xor_sync(0xFFFFFFFFu, p3, o);
    }
    if (l == 0) {
        ((float4*)g_maps)[e] =
            make_float4(p0 + b_map2[0], p1 + b_map2[1], p2 + b_map2[2], p3 + b_map2[3]);
    }
}

// ---------------- per-node: diag = segsum(F^T F), Dinv, diag_n ----------------
__global__ void node_diag_k() {
    int n = blockIdx.x * blockDim.x + threadIdx.x;
    if (n >= NN) return;
    float f00 = 0.f, f01 = 0.f, f11 = 0.f;
    int beg = g_rowptr[n], end = g_rowptr[n + 1];
    const float4* maps4 = (const float4*)g_maps;
    for (int i = beg; i < end; i++) {
        float4 m = maps4[g_adj[i]];
        f00 += m.x * m.x + m.z * m.z;
        f01 += m.x * m.y + m.z * m.w;
        f11 += m.y * m.y + m.w * m.w;
    }
    float t = 0.5f * (f00 + f11);
    float dd = 0.5f * (f00 - f11);
    float rad = sqrtf(dd * dd + f01 * f01);
    float l1 = t - rad, l2 = t + rad;
    float s1 = rsqrtf(fmaxf(l1, EPSV));
    float s2 = rsqrtf(fmaxf(l2, EPSV));
    float c0 = 0.5f * (s1 + s2);
    float c1 = (rad > 1e-20f) ? (s2 - s1) / (2.f * rad) : 0.f;
    float D00 = c0 + c1 * dd;
    float D01 = c1 * f01;
    float D11 = c0 - c1 * dd;
    float g00 = f00 * D00 + f01 * D01, g01 = f00 * D01 + f01 * D11;
    float g10 = f01 * D00 + f11 * D01, g11 = f01 * D01 + f11 * D11;
    float dn00 = D00 * g00 + D01 * g10, dn01 = D00 * g01 + D01 * g11;
    float dn10 = D01 * g00 + D11 * g10, dn11 = D01 * g01 + D11 * g11;
    ((float4*)g_Dinv)[n] = make_float4(D00, D01, D01, D11);
    ((float4*)g_diagn)[n] = make_float4(dn00, dn01, dn10, dn11);
}

// ---------------- per-edge normalized off-diagonal blocks ----------------
__global__ void edge_offn_k(const int* __restrict__ src, const int* __restrict__ dst) {
    int e = blockIdx.x * blockDim.x + threadIdx.x;
    if (e >= EE) return;
    int r = (e < EH) ? e + EH : e - EH;
    const float4* maps4 = (const float4*)g_maps;
    float4 me = maps4[e];
    float4 mr = maps4[r];
    float o00 = -(me.x * mr.x + me.z * mr.z);
    float o01 = -(me.x * mr.y + me.z * mr.w);
    float o10 = -(me.y * mr.x + me.w * mr.z);
    float o11 = -(me.y * mr.y + me.w * mr.w);
    float4 Ds = ((const float4*)g_Dinv)[src[e]];
    float4 Dd = ((const float4*)g_Dinv)[dst[e]];
    float t00 = Ds.x * o00 + Ds.y * o10, t01 = Ds.x * o01 + Ds.y * o11;
    float t10 = Ds.z * o00 + Ds.w * o10, t11 = Ds.z * o01 + Ds.w * o11;
    float n00 = t00 * Dd.x + t01 * Dd.z, n01 = t00 * Dd.y + t01 * Dd.w;
    float n10 = t10 * Dd.x + t11 * Dd.z, n11 = t10 * Dd.y + t11 * Dd.w;
    ((float4*)g_offn)[e] = make_float4(n00, n01, n10, n11);
}

// ---------------- gather-based sheaf aggregation + elu update (warp per node) -------------
__global__ void __launch_bounds__(256) aggregate_k(const int* __restrict__ dst) {
    int w = threadIdx.x >> 5, l = threadIdx.x & 31;
    int n = blockIdx.x * 8 + w;
    if (n >= NN) return;
    const float* Hn = g_Ht + (size_t)n * 128;
    float ht0a = Hn[l], ht0b = Hn[32 + l], ht1a = Hn[64 + l], ht1b = Hn[96 + l];
    float4 dn = ((const float4*)g_diagn)[n];
    float a0a = dn.x * ht0a + dn.y * ht1a;
    float a0b = dn.x * ht0b + dn.y * ht1b;
    float a1a = dn.z * ht0a + dn.w * ht1a;
    float a1b = dn.z * ht0b + dn.w * ht1b;
    int beg = g_rowptr[n], end = g_rowptr[n + 1];
    const float4* offn4 = (const float4*)g_offn;
    for (int i = beg; i < end; i++) {
        int e = g_adj[i];
        int dd = dst[e];
        float4 o = offn4[e];
        const float* H = g_Ht + (size_t)dd * 128;
        float x0a = H[l], x0b = H[32 + l], x1a = H[64 + l], x1b = H[96 + l];
        a0a += o.x * x0a + o.y * x1a;
        a0b += o.x * x0b + o.y * x1b;
        a1a += o.z * x0a + o.w * x1a;
        a1b += o.z * x0b + o.w * x1b;
    }
    float* h3 = g_h + (size_t)n * 128;
    h3[l] -= eluf(a0a);
    h3[32 + l] -= eluf(a0b);
    h3[64 + l] -= eluf(a1a);
    h3[96 + l] -= eluf(a1b);
}

// ---------------- host ----------------
extern "C" void kernel_launch(void* const* d_in, const int* in_sizes, int n_in,
                              void* d_out, int out_size) {
    (void)in_sizes; (void)n_in; (void)out_size;
    const float* x = (const float*)d_in[0];
    const int* ei = (const int*)d_in[1];
    const int* src = ei;
    const int* dst = ei + EE;
    const float* w_in1 = (const float*)d_in[2];
    const float* b_in1 = (const float*)d_in[3];
    const float* w_in2 = (const float*)d_in[4];
    const float* b_in2 = (const float*)d_in[5];
    const float* w_map1 = (const float*)d_in[6];
    const float* b_map1 = (const float*)d_in[7];
    const float* w_map2 = (const float*)d_in[8];
    const float* b_map2 = (const float*)d_in[9];
    const float* w_out1 = (const float*)d_in[10];
    const float* b_out1 = (const float*)d_in[11];
    const float* w_out2 = (const float*)d_in[12];
    const float* b_out2 = (const float*)d_in[13];
    const float* W1_0 = (const float*)d_in[14];
    const float* W2_0 = (const float*)d_in[15];
    const float* W1_1 = (const float*)d_in[16];
    const float* W2_1 = (const float*)d_in[17];
    float* out = (float*)d_out;

    void *p_h1, *p_h, *p_P, *p_Wab, *p_We0, *p_We1, *p_Ht;
    cudaGetSymbolAddress(&p_h1, g_h1);
    cudaGetSymbolAddress(&p_h, g_h);
    cudaGetSymbolAddress(&p_P, g_P);
    cudaGetSymbolAddress(&p_Wab, g_Wab);
    cudaGetSymbolAddress(&p_We0, g_Weff0);
    cudaGetSymbolAddress(&p_We1, g_Weff1);
    cudaGetSymbolAddress(&p_Ht, g_Ht);

    const int MB = (NN + 127) / 128;  // 157

    prep_k<<<79, 256>>>(w_map1, W1_0, W2_0, W1_1, W2_1);

    // input MLP
    gemm_mma<64, true><<<dim3(1, MB), 256>>>(x, w_in1, b_in1, (float*)p_h1, NN, 64, 512);
    gemm_mma<128, false><<<dim3(1, MB), 256>>>((const float*)p_h1, w_in2, b_in2,
                                               (float*)p_h, NN, 128, 64);
    // per-node A|B partials for the edge MLP
    gemm_mma<128, false><<<dim3(1, MB), 256>>>((const float*)p_h, (const float*)p_Wab,
                                               nullptr, (float*)p_P, NN, 128, 128);

    // CSR by src
    hist_k<<<1250, 256>>>(src);
    scan_k<<<1, 1024>>>();
    scatter_k<<<1250, 256>>>(src);

    // edge maps, diag blocks, off blocks
    edge_maps_k<<<EE / 8, 256>>>(src, dst, b_map1, w_map2, b_map2);
    node_diag_k<<<79, 256>>>();
    edge_offn_k<<<1250, 256>>>(src, dst);

    // two sheaf-diffusion layers: Ht = h3 @ Weff^T (fused W1/W2), then aggregate
    const float* We[2] = {(const float*)p_We0, (const float*)p_We1};
    for (int layer = 0; layer < 2; layer++) {
        gemm_mma<128, false><<<dim3(1, MB), 256>>>((const float*)p_h, We[layer], nullptr,
                                                   (float*)p_Ht, NN, 128, 128);
        aggregate_k<<<2500, 256>>>(dst);
    }

    // output MLP
    gemm_mma<64, true><<<dim3(1, MB), 256>>>((const float*)p_h, w_out1, b_out1,
                                             (float*)p_h1, NN, 64, 128);
    gemm_mma<64, false><<<dim3(1, MB), 256>>>((const float*)p_h1, w_out2, b_out2, out,
                                              NN, 40, 64);
}

// round 5
// speedup vs baseline: 1.5317x; 1.0591x over previous
#include <cuda_runtime.h>
#include <cuda_bf16.h>
#include <math.h>
#include <stdint.h>

#define NN 20000
#define EE 320000
#define EH 160000
#define EPSV 1e-6f

// ---------------- scratch (static device globals; no allocs) ----------------
__device__ float g_h1[NN * 64];
__device__ float g_h[NN * 128];
__device__ float g_P[NN * 128];
__device__ float g_Wab[128 * 128];
__device__ float g_Weff0[128 * 128];
__device__ float g_Weff1[128 * 128];
__device__ float g_maps[EE * 4];       // edge restriction maps (edge order)
__device__ float g_Dinv[NN * 4];
__device__ float g_diagn[NN * 4];
__device__ float g_offn[EE * 4];       // normalized off-diag blocks (CSR order!)
__device__ float g_Ht[NN * 128];
__device__ int g_deg[NN];
__device__ int g_cursor[NN];
__device__ int g_rowptr[NN + 1];
__device__ int g_adj[EE];              // CSR -> edge id (for node_diag)
__device__ int g_dstc[EE];             // CSR -> dst node
__device__ int g_pos[EE];              // edge id -> CSR slot

__device__ __forceinline__ float eluf(float v) {
    return v > 0.f ? v : (expf(v) - 1.f);
}

__device__ __forceinline__ uint32_t packbf(__nv_bfloat16 a, __nv_bfloat16 b) {
    __nv_bfloat162 t = __halves2bfloat162(a, b);
    return *reinterpret_cast<uint32_t*>(&t);
}

#define MMA16816(c, a, b0_, b1_)                                             \
    asm volatile(                                                            \
        "mma.sync.aligned.m16n8k16.row.col.f32.bf16.bf16.f32 "               \
        "{%0,%1,%2,%3}, {%4,%5,%6,%7}, {%8,%9}, {%0,%1,%2,%3};"              \
        : "+f"((c)[0]), "+f"((c)[1]), "+f"((c)[2]), "+f"((c)[3])             \
        : "r"((a)[0]), "r"((a)[1]), "r"((a)[2]), "r"((a)[3]),                \
          "r"(b0_), "r"(b1_))

// ---------------- tensor-core GEMM: C = act(A[M,K] @ W[N,K]^T + bias) ----------------
// bf16 hi/lo split (3 MMA products) -> fp32-equivalent accuracy.
// BM=64, BN in {128,64}, BK=16, 256 threads (8 warps: 2 along M, 4 along N).
template <int BN, bool RELU>
__global__ void __launch_bounds__(256) gemm_mma(const float* __restrict__ A,
                                                const float* __restrict__ W,
                                                const float* __restrict__ bias,
                                                float* __restrict__ C,
                                                int M, int N, int K) {
    constexpr int BM = 64;
    constexpr int WN = BN / 4;     // warp tile cols
    constexpr int NSUB = WN / 8;   // n-subtiles per warp (4 or 2)
    constexpr int SW = 12;         // smem words per row (8 data + 4 pad)

    __shared__ uint32_t sAh[BM * SW], sAl[BM * SW];
    __shared__ uint32_t sWh[BN * SW], sWl[BN * SW];

    const int tid = threadIdx.x;
    const int lane = tid & 31;
    const int wid = tid >> 5;
    const int warp_m = wid & 1;
    const int warp_n = wid >> 1;
    const int qr = lane >> 2;  // 0..7
    const int qc = lane & 3;   // 0..3

    const int bm = blockIdx.y * BM;
    const int bn = blockIdx.x * BN;

    const int lm = tid >> 2;       // loader row 0..63
    const int lk = (tid & 3) * 4;  // loader k-offset (floats)
    const int wof = lk >> 1;       // word offset within smem row

    float acc[2][NSUB][4];
#pragma unroll
    for (int i = 0; i < 2; i++)
#pragma unroll
        for (int j = 0; j < NSUB; j++)
#pragma unroll
            for (int q = 0; q < 4; q++) acc[i][j][q] = 0.f;

    float4 a_reg;
    float4 w_reg[BN / 64];

    auto loadA = [&](int k0) {
        int m = bm + lm;
        a_reg = (m < M) ? *(const float4*)(A + (size_t)m * K + k0 + lk)
                        : make_float4(0.f, 0.f, 0.f, 0.f);
    };
    auto loadW = [&](int k0) {
#pragma unroll
        for (int i = 0; i < BN / 64; i++) {
            int n = bn + lm + i * 64;
            w_reg[i] = (n < N) ? *(const float4*)(W + (size_t)n * K + k0 + lk)
                               : make_float4(0.f, 0.f, 0.f, 0.f);
        }
    };

    auto storeSplit = [&](uint32_t* hi, uint32_t* lo, int row, float4 v) {
        __nv_bfloat16 h0 = __float2bfloat16(v.x), h1 = __float2bfloat16(v.y);
        __nv_bfloat16 h2 = __float2bfloat16(v.z), h3 = __float2bfloat16(v.w);
        __nv_bfloat16 l0 = __float2bfloat16(v.x - __bfloat162float(h0));
        __nv_bfloat16 l1 = __float2bfloat16(v.y - __bfloat162float(h1));
        __nv_bfloat16 l2 = __float2bfloat16(v.z - __bfloat162float(h2));
        __nv_bfloat16 l3 = __float2bfloat16(v.w - __bfloat162float(h3));
        int w0 = row * SW + wof;
        hi[w0 + 0] = packbf(h0, h1);
        hi[w0 + 1] = packbf(h2, h3);
        lo[w0 + 0] = packbf(l0, l1);
        lo[w0 + 1] = packbf(l2, l3);
    };

    loadA(0);
    loadW(0);

    for (int k0 = 0; k0 < K; k0 += 16) {
        storeSplit(sAh, sAl, lm, a_reg);
#pragma unroll
        for (int i = 0; i < BN / 64; i++) storeSplit(sWh, sWl, lm + i * 64, w_reg[i]);
        __syncthreads();

        if (k0 + 16 < K) {
            loadA(k0 + 16);
            loadW(k0 + 16);
        }

        uint32_t ah[2][4], al[2][4];
#pragma unroll
        for (int ms = 0; ms < 2; ms++) {
            int r = warp_m * 32 + ms * 16 + qr;
            int b0 = r * SW + qc;
            ah[ms][0] = sAh[b0];
            ah[ms][1] = sAh[b0 + 8 * SW];
            ah[ms][2] = sAh[b0 + 4];
            ah[ms][3] = sAh[b0 + 8 * SW + 4];
            al[ms][0] = sAl[b0];
            al[ms][1] = sAl[b0 + 8 * SW];
            al[ms][2] = sAl[b0 + 4];
            al[ms][3] = sAl[b0 + 8 * SW + 4];
        }

#pragma unroll
        for (int ns = 0; ns < NSUB; ns++) {
            int n = warp_n * WN + ns * 8 + qr;
            int b = n * SW + qc;
            uint32_t bh0 = sWh[b], bh1 = sWh[b + 4];
            uint32_t bl0 = sWl[b], bl1 = sWl[b + 4];
#pragma unroll
            for (int ms = 0; ms < 2; ms++) {
                MMA16816(acc[ms][ns], ah[ms], bh0, bh1);
                MMA16816(acc[ms][ns], ah[ms], bl0, bl1);
                MMA16816(acc[ms][ns], al[ms], bh0, bh1);
            }
        }
        __syncthreads();
    }

#pragma unroll
    for (int ms = 0; ms < 2; ms++) {
#pragma unroll
        for (int ns = 0; ns < NSUB; ns++) {
            int m0 = bm + warp_m * 32 + ms * 16 + qr;
            int n0 = bn + warp_n * WN + ns * 8 + 2 * qc;
            const float* c = acc[ms][ns];
#pragma unroll
            for (int half = 0; half < 2; half++) {
                int m = m0 + half * 8;
                if (m >= M) continue;
                float v0 = c[half * 2 + 0];
                float v1 = c[half * 2 + 1];
                if (n0 + 1 < N) {
                    v0 += bias ? bias[n0] : 0.f;
                    v1 += bias ? bias[n0 + 1] : 0.f;
                    if (RELU) { v0 = fmaxf(v0, 0.f); v1 = fmaxf(v1, 0.f); }
                    *(float2*)(C + (size_t)m * N + n0) = make_float2(v0, v1);
                } else if (n0 < N) {
                    v0 += bias ? bias[n0] : 0.f;
                    if (RELU) v0 = fmaxf(v0, 0.f);
                    C[(size_t)m * N + n0] = v0;
                }
            }
        }
    }
}

// ---------------- prep: pack Wab, build Weff kron weights, zero counters ----------------
__global__ void prep_k(const float* __restrict__ w_map1,
                       const float* __restrict__ W1_0, const float* __restrict__ W2_0,
                       const float* __restrict__ W1_1, const float* __restrict__ W2_1) {
    int i = blockIdx.x * blockDim.x + threadIdx.x;
    if (i < 128 * 128) {
        int j = i >> 7, k = i & 127;
        g_Wab[i] = (j < 64) ? w_map1[j * 256 + k] : w_map1[(j - 64) * 256 + 128 + k];
        int r = i >> 7, c = i & 127;
        int ii = r >> 6, g = r & 63;
        int jj = c >> 6, f = c & 63;
        g_Weff0[i] = W1_0[jj * 2 + ii] * W2_0[g * 64 + f];
        g_Weff1[i] = W1_1[jj * 2 + ii] * W2_1[g * 64 + f];
    }
    if (i < NN) {
        g_deg[i] = 0;
        g_cursor[i] = 0;
    }
}

// ---------------- CSR build ----------------
__global__ void hist_k(const int* __restrict__ src) {
    int e = blockIdx.x * blockDim.x + threadIdx.x;
    if (e < EE) atomicAdd(&g_deg[src[e]], 1);
}

__global__ void __launch_bounds__(1024) scan_k() {
    __shared__ int wsum[32];
    __shared__ int carry;
    int t = threadIdx.x, l = t & 31, w = t >> 5;
    if (t == 0) { carry = 0; g_rowptr[0] = 0; }
    __syncthreads();
    for (int base = 0; base < NN; base += 1024) {
        int v = (base + t < NN) ? g_deg[base + t] : 0;
        int x = v;
#pragma unroll
        for (int o = 1; o < 32; o <<= 1) {
            int y = __shfl_up_sync(0xFFFFFFFFu, x, o);
            if (l >= o) x += y;
        }
        if (l == 31) wsum[w] = x;
        __syncthreads();
        if (w == 0) {
            int y = wsum[l];
#pragma unroll
            for (int o = 1; o < 32; o <<= 1) {
                int z = __shfl_up_sync(0xFFFFFFFFu, y, o);
                if (l >= o) y += z;
            }
            wsum[l] = y;
        }
        __syncthreads();
        int off = carry + (w > 0 ? wsum[w - 1] : 0);
        if (base + t < NN) g_rowptr[base + t + 1] = off + x;
        __syncthreads();
        if (t == 0) carry += wsum[31];
        __syncthreads();
    }
}

__global__ void scatter_k(const int* __restrict__ src, const int* __restrict__ dst) {
    int e = blockIdx.x * blockDim.x + threadIdx.x;
    if (e < EE) {
        int s = src[e];
        int p = atomicAdd(&g_cursor[s], 1);
        int pos = g_rowptr[s] + p;
        g_adj[pos] = e;
        g_dstc[pos] = dst[e];
        g_pos[e] = pos;
    }
}

// ---------------- edge restriction maps (warp per edge) ----------------
__global__ void __launch_bounds__(256) edge_maps_k(const int* __restrict__ src,
                                                   const int* __restrict__ dst,
                                                   const float* __restrict__ b_map1,
                                                   const float* __restrict__ w_map2,
                                                   const float* __restrict__ b_map2) {
    int w = threadIdx.x >> 5, l = threadIdx.x & 31;
    int e = blockIdx.x * 8 + w;
    if (e >= EE) return;
    int s = src[e], d = dst[e];
    float h0 = g_P[s * 128 + l] + g_P[d * 128 + 64 + l] + b_map1[l];
    float h1 = g_P[s * 128 + 32 + l] + g_P[d * 128 + 96 + l] + b_map1[32 + l];
    h0 = fmaxf(h0, 0.f);
    h1 = fmaxf(h1, 0.f);
    float p0 = h0 * w_map2[l] + h1 * w_map2[32 + l];
    float p1 = h0 * w_map2[64 + l] + h1 * w_map2[96 + l];
    float p2 = h0 * w_map2[128 + l] + h1 * w_map2[160 + l];
    float p3 = h0 * w_map2[192 + l] + h1 * w_map2[224 + l];
#pragma unroll
    for (int o = 16; o > 0; o >>= 1) {
        p0 += __shfl_xor_sync(0xFFFFFFFFu, p0, o);
        p1 += __shfl_xor_sync(0xFFFFFFFFu, p1, o);
        p2 += __shfl_xor_sync(0xFFFFFFFFu, p2, o);
        p3 += __shfl_xor_sync(0xFFFFFFFFu, p3, o);
    }
    if (l == 0) {
        ((float4*)g_maps)[e] =
            make_float4(p0 + b_map2[0], p1 + b_map2[1], p2 + b_map2[2], p3 + b_map2[3]);
    }
}

// ---------------- per-node: diag = segsum(F^T F), Dinv, diag_n ----------------
__global__ void node_diag_k() {
    int n = blockIdx.x * blockDim.x + threadIdx.x;
    if (n >= NN) return;
    float f00 = 0.f, f01 = 0.f, f11 = 0.f;
    int beg = g_rowptr[n], end = g_rowptr[n + 1];
    const float4* maps4 = (const float4*)g_maps;
    for (int i = beg; i < end; i++) {
        float4 m = maps4[g_adj[i]];
        f00 += m.x * m.x + m.z * m.z;
        f01 += m.x * m.y + m.z * m.w;
        f11 += m.y * m.y + m.w * m.w;
    }
    float t = 0.5f * (f00 + f11);
    float dd = 0.5f * (f00 - f11);
    float rad = sqrtf(dd * dd + f01 * f01);
    float l1 = t - rad, l2 = t + rad;
    float s1 = rsqrtf(fmaxf(l1, EPSV));
    float s2 = rsqrtf(fmaxf(l2, EPSV));
    float c0 = 0.5f * (s1 + s2);
    float c1 = (rad > 1e-20f) ? (s2 - s1) / (2.f * rad) : 0.f;
    float D00 = c0 + c1 * dd;
    float D01 = c1 * f01;
    float D11 = c0 - c1 * dd;
    float g00 = f00 * D00 + f01 * D01, g01 = f00 * D01 + f01 * D11;
    float g10 = f01 * D00 + f11 * D01, g11 = f01 * D01 + f11 * D11;
    float dn00 = D00 * g00 + D01 * g10, dn01 = D00 * g01 + D01 * g11;
    float dn10 = D01 * g00 + D11 * g10, dn11 = D01 * g01 + D11 * g11;
    ((float4*)g_Dinv)[n] = make_float4(D00, D01, D01, D11);
    ((float4*)g_diagn)[n] = make_float4(dn00, dn01, dn10, dn11);
}

// ---------------- per-edge normalized off-diagonal blocks (write CSR order) -------------
__global__ void edge_offn_k(const int* __restrict__ src, const int* __restrict__ dst) {
    int e = blockIdx.x * blockDim.x + threadIdx.x;
    if (e >= EE) return;
    int r = (e < EH) ? e + EH : e - EH;
    const float4* maps4 = (const float4*)g_maps;
    float4 me = maps4[e];
    float4 mr = maps4[r];
    float o00 = -(me.x * mr.x + me.z * mr.z);
    float o01 = -(me.x * mr.y + me.z * mr.w);
    float o10 = -(me.y * mr.x + me.w * mr.z);
    float o11 = -(me.y * mr.y + me.w * mr.w);
    float4 Ds = ((const float4*)g_Dinv)[src[e]];
    float4 Dd = ((const float4*)g_Dinv)[dst[e]];
    float t00 = Ds.x * o00 + Ds.y * o10, t01 = Ds.x * o01 + Ds.y * o11;
    float t10 = Ds.z * o00 + Ds.w * o10, t11 = Ds.z * o01 + Ds.w * o11;
    float n00 = t00 * Dd.x + t01 * Dd.z, n01 = t00 * Dd.y + t01 * Dd.w;
    float n10 = t10 * Dd.x + t11 * Dd.z, n11 = t10 * Dd.y + t11 * Dd.w;
    ((float4*)g_offn)[g_pos[e]] = make_float4(n00, n01, n10, n11);
}

// ---------------- gather-based sheaf aggregation + elu update (warp per node) -------------
__global__ void __launch_bounds__(256) aggregate_k() {
    int w = threadIdx.x >> 5, l = threadIdx.x & 31;
    int n = blockIdx.x * 8 + w;
    if (n >= NN) return;
    const float* Hn = g_Ht + (size_t)n * 128;
    float ht0a = Hn[l], ht0b = Hn[32 + l], ht1a = Hn[64 + l], ht1b = Hn[96 + l];
    float4 dn = ((const float4*)g_diagn)[n];
    float a0a = dn.x * ht0a + dn.y * ht1a;
    float a0b = dn.x * ht0b + dn.y * ht1b;
    float a1a = dn.z * ht0a + dn.w * ht1a;
    float a1b = dn.z * ht0b + dn.w * ht1b;
    int beg = g_rowptr[n], end = g_rowptr[n + 1];
    const float4* offn4 = (const float4*)g_offn;
    int i = beg;
    for (; i + 2 <= end; i += 2) {
        float4 o0 = offn4[i];
        float4 o1 = offn4[i + 1];
        int d0 = g_dstc[i];
        int d1 = g_dstc[i + 1];
        const float* H0 = g_Ht + (size_t)d0 * 128;
        const float* H1 = g_Ht + (size_t)d1 * 128;
        float x0a = H0[l], x0b = H0[32 + l], x1a = H0[64 + l], x1b = H0[96 + l];
        float y0a = H1[l], y0b = H1[32 + l], y1a = H1[64 + l], y1b = H1[96 + l];
        a0a += o0.x * x0a + o0.y * x1a;
        a0b += o0.x * x0b + o0.y * x1b;
        a1a += o0.z * x0a + o0.w * x1a;
        a1b += o0.z * x0b + o0.w * x1b;
        a0a += o1.x * y0a + o1.y * y1a;
        a0b += o1.x * y0b + o1.y * y1b;
        a1a += o1.z * y0a + o1.w * y1a;
        a1b += o1.z * y0b + o1.w * y1b;
    }
    for (; i < end; i++) {
        float4 o = offn4[i];
        int dd = g_dstc[i];
        const float* H = g_Ht + (size_t)dd * 128;
        float x0a = H[l], x0b = H[32 + l], x1a = H[64 + l], x1b = H[96 + l];
        a0a += o.x * x0a + o.y * x1a;
        a0b += o.x * x0b + o.y * x1b;
        a1a += o.z * x0a + o.w * x1a;
        a1b += o.z * x0b + o.w * x1b;
    }
    float* h3 = g_h + (size_t)n * 128;
    h3[l] -= eluf(a0a);
    h3[32 + l] -= eluf(a0b);
    h3[64 + l] -= eluf(a1a);
    h3[96 + l] -= eluf(a1b);
}

// ---------------- host ----------------
extern "C" void kernel_launch(void* const* d_in, const int* in_sizes, int n_in,
                              void* d_out, int out_size) {
    (void)in_sizes; (void)n_in; (void)out_size;
    const float* x = (const float*)d_in[0];
    const int* ei = (const int*)d_in[1];
    const int* src = ei;
    const int* dst = ei + EE;
    const float* w_in1 = (const float*)d_in[2];
    const float* b_in1 = (const float*)d_in[3];
    const float* w_in2 = (const float*)d_in[4];
    const float* b_in2 = (const float*)d_in[5];
    const float* w_map1 = (const float*)d_in[6];
    const float* b_map1 = (const float*)d_in[7];
    const float* w_map2 = (const float*)d_in[8];
    const float* b_map2 = (const float*)d_in[9];
    const float* w_out1 = (const float*)d_in[10];
    const float* b_out1 = (const float*)d_in[11];
    const float* w_out2 = (const float*)d_in[12];
    const float* b_out2 = (const float*)d_in[13];
    const float* W1_0 = (const float*)d_in[14];
    const float* W2_0 = (const float*)d_in[15];
    const float* W1_1 = (const float*)d_in[16];
    const float* W2_1 = (const float*)d_in[17];
    float* out = (float*)d_out;

    void *p_h1, *p_h, *p_P, *p_Wab, *p_We0, *p_We1, *p_Ht;
    cudaGetSymbolAddress(&p_h1, g_h1);
    cudaGetSymbolAddress(&p_h, g_h);
    cudaGetSymbolAddress(&p_P, g_P);
    cudaGetSymbolAddress(&p_Wab, g_Wab);
    cudaGetSymbolAddress(&p_We0, g_Weff0);
    cudaGetSymbolAddress(&p_We1, g_Weff1);
    cudaGetSymbolAddress(&p_Ht, g_Ht);

    const int MB = (NN + 63) / 64;  // 313

    prep_k<<<79, 256>>>(w_map1, W1_0, W2_0, W1_1, W2_1);

    // CSR by src (independent of MLPs)
    hist_k<<<1250, 256>>>(src);
    scan_k<<<1, 1024>>>();
    scatter_k<<<1250, 256>>>(src, dst);

    // input MLP
    gemm_mma<64, true><<<dim3(1, MB), 256>>>(x, w_in1, b_in1, (float*)p_h1, NN, 64, 512);
    gemm_mma<128, false><<<dim3(1, MB), 256>>>((const float*)p_h1, w_in2, b_in2,
                                               (float*)p_h, NN, 128, 64);
    // per-node A|B partials for the edge MLP
    gemm_mma<128, false><<<dim3(1, MB), 256>>>((const float*)p_h, (const float*)p_Wab,
                                               nullptr, (float*)p_P, NN, 128, 128);

    // edge maps, diag blocks, off blocks
    edge_maps_k<<<EE / 8, 256>>>(src, dst, b_map1, w_map2, b_map2);
    node_diag_k<<<79, 256>>>();
    edge_offn_k<<<1250, 256>>>(src, dst);

    // two sheaf-diffusion layers: Ht = h3 @ Weff^T (fused W1/W2), then aggregate
    const float* We[2] = {(const float*)p_We0, (const float*)p_We1};
    for (int layer = 0; layer < 2; layer++) {
        gemm_mma<128, false><<<dim3(1, MB), 256>>>((const float*)p_h, We[layer], nullptr,
                                                   (float*)p_Ht, NN, 128, 128);
        aggregate_k<<<2500, 256>>>();
    }

    // output MLP
    gemm_mma<64, true><<<dim3(1, MB), 256>>>((const float*)p_h, w_out1, b_out1,
                                             (float*)p_h1, NN, 64, 128);
    gemm_mma<64, false><<<dim3(1, MB), 256>>>((const float*)p_h1, w_out2, b_out2, out,
                                              NN, 40, 64);
}

// round 6
// speedup vs baseline: 1.5496x; 1.0117x over previous
#include <cuda_runtime.h>
#include <cuda_bf16.h>
#include <math.h>
#include <stdint.h>

#define NN 20000
#define EE 320000
#define EH 160000
#define EPSV 1e-6f

// ---------------- scratch (static device globals; no allocs) ----------------
__device__ float g_h1[NN * 64];
__device__ float g_h[NN * 128];
__device__ float g_P[NN * 128];
__device__ float g_Wab[128 * 128];
__device__ float g_Wc[256 * 64];       // [w_in2 ; Wab@w_in2]
__device__ float g_bP[128];            // Wab @ b_in2
__device__ float g_Weff0[128 * 128];
__device__ float g_Weff1[128 * 128];
__device__ float g_maps[EE * 4];
__device__ float g_Dinv[NN * 4];
__device__ float g_diagn[NN * 4];
__device__ float g_offn[EE * 4];       // CSR order
__device__ float g_Ht[NN * 128];
__device__ int g_deg[NN];
__device__ int g_cursor[NN];
__device__ int g_rowptr[NN + 1];
__device__ int2 g_adjdst[EE];          // CSR slot -> (edge id, dst node)
__device__ int g_pos[EE];              // edge id -> CSR slot

__device__ __forceinline__ float eluf(float v) {
    return v > 0.f ? v : (expf(v) - 1.f);
}

__device__ __forceinline__ uint32_t packbf(__nv_bfloat16 a, __nv_bfloat16 b) {
    __nv_bfloat162 t = __halves2bfloat162(a, b);
    return *reinterpret_cast<uint32_t*>(&t);
}

#define MMA16816(c, a, b0_, b1_)                                             \
    asm volatile(                                                            \
        "mma.sync.aligned.m16n8k16.row.col.f32.bf16.bf16.f32 "               \
        "{%0,%1,%2,%3}, {%4,%5,%6,%7}, {%8,%9}, {%0,%1,%2,%3};"              \
        : "+f"((c)[0]), "+f"((c)[1]), "+f"((c)[2]), "+f"((c)[3])             \
        : "r"((a)[0]), "r"((a)[1]), "r"((a)[2]), "r"((a)[3]),                \
          "r"(b0_), "r"(b1_))

// ---------------- tensor-core GEMM body (device function, callable from merged kernels) --
// C[m*ldc + n] = act(A[M,K] @ W[N,K]^T + bias), bf16 hi/lo split (3 MMA).
// BM=64, 256 threads (8 warps: 2 along M, 4 along N). bm/bn are this block's tile origin.
template <int BN, bool RELU>
__device__ __forceinline__ void gemm_body(const float* __restrict__ A,
                                          const float* __restrict__ W,
                                          const float* __restrict__ bias,
                                          float* __restrict__ C,
                                          int M, int N, int K, int bm, int bn, int ldc) {
    constexpr int BM = 64;
    constexpr int WN = BN / 4;
    constexpr int NSUB = WN / 8;
    constexpr int SW = 12;

    __shared__ uint32_t sAh[BM * SW], sAl[BM * SW];
    __shared__ uint32_t sWh[BN * SW], sWl[BN * SW];

    const int tid = threadIdx.x;
    const int lane = tid & 31;
    const int wid = tid >> 5;
    const int warp_m = wid & 1;
    const int warp_n = wid >> 1;
    const int qr = lane >> 2;
    const int qc = lane & 3;

    const int lm = tid >> 2;
    const int lk = (tid & 3) * 4;
    const int wof = lk >> 1;

    float acc[2][NSUB][4];
#pragma unroll
    for (int i = 0; i < 2; i++)
#pragma unroll
        for (int j = 0; j < NSUB; j++)
#pragma unroll
            for (int q = 0; q < 4; q++) acc[i][j][q] = 0.f;

    float4 a_reg;
    float4 w_reg[BN / 64];

    auto loadA = [&](int k0) {
        int m = bm + lm;
        a_reg = (m < M) ? *(const float4*)(A + (size_t)m * K + k0 + lk)
                        : make_float4(0.f, 0.f, 0.f, 0.f);
    };
    auto loadW = [&](int k0) {
#pragma unroll
        for (int i = 0; i < BN / 64; i++) {
            int n = bn + lm + i * 64;
            w_reg[i] = (n < N) ? *(const float4*)(W + (size_t)n * K + k0 + lk)
                               : make_float4(0.f, 0.f, 0.f, 0.f);
        }
    };

    auto storeSplit = [&](uint32_t* hi, uint32_t* lo, int row, float4 v) {
        __nv_bfloat16 h0 = __float2bfloat16(v.x), h1 = __float2bfloat16(v.y);
        __nv_bfloat16 h2 = __float2bfloat16(v.z), h3 = __float2bfloat16(v.w);
        __nv_bfloat16 l0 = __float2bfloat16(v.x - __bfloat162float(h0));
        __nv_bfloat16 l1 = __float2bfloat16(v.y - __bfloat162float(h1));
        __nv_bfloat16 l2 = __float2bfloat16(v.z - __bfloat162float(h2));
        __nv_bfloat16 l3 = __float2bfloat16(v.w - __bfloat162float(h3));
        int w0 = row * SW + wof;
        hi[w0 + 0] = packbf(h0, h1);
        hi[w0 + 1] = packbf(h2, h3);
        lo[w0 + 0] = packbf(l0, l1);
        lo[w0 + 1] = packbf(l2, l3);
    };

    loadA(0);
    loadW(0);

    for (int k0 = 0; k0 < K; k0 += 16) {
        storeSplit(sAh, sAl, lm, a_reg);
#pragma unroll
        for (int i = 0; i < BN / 64; i++) storeSplit(sWh, sWl, lm + i * 64, w_reg[i]);
        __syncthreads();

        if (k0 + 16 < K) {
            loadA(k0 + 16);
            loadW(k0 + 16);
        }

        uint32_t ah[2][4], al[2][4];
#pragma unroll
        for (int ms = 0; ms < 2; ms++) {
            int r = warp_m * 32 + ms * 16 + qr;
            int b0 = r * SW + qc;
            ah[ms][0] = sAh[b0];
            ah[ms][1] = sAh[b0 + 8 * SW];
            ah[ms][2] = sAh[b0 + 4];
            ah[ms][3] = sAh[b0 + 8 * SW + 4];
            al[ms][0] = sAl[b0];
            al[ms][1] = sAl[b0 + 8 * SW];
            al[ms][2] = sAl[b0 + 4];
            al[ms][3] = sAl[b0 + 8 * SW + 4];
        }

#pragma unroll
        for (int ns = 0; ns < NSUB; ns++) {
            int n = warp_n * WN + ns * 8 + qr;
            int b = n * SW + qc;
            uint32_t bh0 = sWh[b], bh1 = sWh[b + 4];
            uint32_t bl0 = sWl[b], bl1 = sWl[b + 4];
#pragma unroll
            for (int ms = 0; ms < 2; ms++) {
                MMA16816(acc[ms][ns], ah[ms], bh0, bh1);
                MMA16816(acc[ms][ns], ah[ms], bl0, bl1);
                MMA16816(acc[ms][ns], al[ms], bh0, bh1);
            }
        }
        __syncthreads();
    }

#pragma unroll
    for (int ms = 0; ms < 2; ms++) {
#pragma unroll
        for (int ns = 0; ns < NSUB; ns++) {
            int m0 = bm + warp_m * 32 + ms * 16 + qr;
            int n0 = bn + warp_n * WN + ns * 8 + 2 * qc;
            const float* c = acc[ms][ns];
#pragma unroll
            for (int half = 0; half < 2; half++) {
                int m = m0 + half * 8;
                if (m >= M) continue;
                float v0 = c[half * 2 + 0];
                float v1 = c[half * 2 + 1];
                if (n0 + 1 < N) {
                    v0 += bias ? bias[n0] : 0.f;
                    v1 += bias ? bias[n0 + 1] : 0.f;
                    if (RELU) { v0 = fmaxf(v0, 0.f); v1 = fmaxf(v1, 0.f); }
                    *(float2*)(C + (size_t)m * ldc + n0) = make_float2(v0, v1);
                } else if (n0 < N) {
                    v0 += bias ? bias[n0] : 0.f;
                    if (RELU) v0 = fmaxf(v0, 0.f);
                    C[(size_t)m * ldc + n0] = v0;
                }
            }
        }
    }
}

// ---------------- prep: pack Wab, build Weff kron weights, zero counters ----------------
__global__ void prep_k(const float* __restrict__ w_map1,
                       const float* __restrict__ W1_0, const float* __restrict__ W2_0,
                       const float* __restrict__ W1_1, const float* __restrict__ W2_1) {
    int i = blockIdx.x * blockDim.x + threadIdx.x;
    if (i < 128 * 128) {
        int j = i >> 7, k = i & 127;
        g_Wab[i] = (j < 64) ? w_map1[j * 256 + k] : w_map1[(j - 64) * 256 + 128 + k];
        int r = i >> 7, c = i & 127;
        int ii = r >> 6, g = r & 63;
        int jj = c >> 6, f = c & 63;
        g_Weff0[i] = W1_0[jj * 2 + ii] * W2_0[g * 64 + f];
        g_Weff1[i] = W1_1[jj * 2 + ii] * W2_1[g * 64 + f];
    }
    if (i < NN) {
        g_deg[i] = 0;
        g_cursor[i] = 0;
    }
}

// ---------------- K1: input-MLP gemm (313) || hist (1250) || weight combine (32) --------
__global__ void __launch_bounds__(256) k1_k(const float* __restrict__ x,
                                            const float* __restrict__ w_in1,
                                            const float* __restrict__ b_in1,
                                            const int* __restrict__ src,
                                            const float* __restrict__ w_in2,
                                            const float* __restrict__ b_in2) {
    int b = blockIdx.x;
    if (b < 313) {
        gemm_body<64, true>(x, w_in1, b_in1, g_h1, NN, 64, 512, b * 64, 0, 64);
    } else if (b < 1563) {
        int e = (b - 313) * 256 + threadIdx.x;
        if (e < EE) atomicAdd(&g_deg[src[e]], 1);
    } else {
        int g = (b - 1563) * 256 + threadIdx.x;  // 0..8191
        g_Wc[g] = w_in2[g];                      // rows 0..127 = w_in2
        int i = g >> 6, k = g & 63;
        float s = 0.f;
#pragma unroll 4
        for (int j = 0; j < 128; j++) s += g_Wab[i * 128 + j] * w_in2[j * 64 + k];
        g_Wc[8192 + g] = s;                      // rows 128..255 = Wab @ w_in2
        if (g < 128) {
            float sb = 0.f;
            for (int j = 0; j < 128; j++) sb += g_Wab[g * 128 + j] * b_in2[j];
            g_bP[g] = sb;
        }
    }
}

// ---------------- scan body (256 threads, 1 block) ----------------
__device__ void scan_body() {
    __shared__ int wsum[8];
    __shared__ int carry;
    int t = threadIdx.x, l = t & 31, w = t >> 5;
    if (t == 0) { carry = 0; g_rowptr[0] = 0; }
    __syncthreads();
    for (int base = 0; base < NN; base += 256) {
        int v = (base + t < NN) ? g_deg[base + t] : 0;
        int x = v;
#pragma unroll
        for (int o = 1; o < 32; o <<= 1) {
            int y = __shfl_up_sync(0xFFFFFFFFu, x, o);
            if (l >= o) x += y;
        }
        if (l == 31) wsum[w] = x;
        __syncthreads();
        if (w == 0 && l < 8) {
            int y = wsum[l];
#pragma unroll
            for (int o = 1; o < 8; o <<= 1) {
                int z = __shfl_up_sync(0xFFu, y, o);
                if (l >= o) y += z;
            }
            wsum[l] = y;
        }
        __syncthreads();
        int off = carry + (w > 0 ? wsum[w - 1] : 0);
        if (base + t < NN) g_rowptr[base + t + 1] = off + x;
        __syncthreads();
        if (t == 0) carry += wsum[7];
        __syncthreads();
    }
}

// ---------------- K2: fused h+P gemm (626) || scan (1) ----------------
__global__ void __launch_bounds__(256) k2_k(const float* __restrict__ b_in2) {
    int b = blockIdx.x;
    if (b < 626) {
        int bm = (b >> 1) * 64;
        int bn = (b & 1) * 128;
        if (bn == 0) {
            gemm_body<128, false>(g_h1, g_Wc, b_in2, g_h, NN, 256, 64, bm, 0, 128);
        } else {
            gemm_body<128, false>(g_h1, g_Wc, g_bP - 128, g_P - 128, NN, 256, 64, bm, 128,
                                  128);
        }
    } else {
        scan_body();
    }
}

// ---------------- K3: edge maps (40000, warp per edge) || scatter (1250) ----------------
__global__ void __launch_bounds__(256) k3_k(const int* __restrict__ src,
                                            const int* __restrict__ dst,
                                            const float* __restrict__ b_map1,
                                            const float* __restrict__ w_map2,
                                            const float* __restrict__ b_map2) {
    int b = blockIdx.x;
    if (b < 40000) {
        int w = threadIdx.x >> 5, l = threadIdx.x & 31;
        int e = b * 8 + w;
        int s = src[e], d = dst[e];
        float h0 = g_P[s * 128 + l] + g_P[d * 128 + 64 + l] + b_map1[l];
        float h1 = g_P[s * 128 + 32 + l] + g_P[d * 128 + 96 + l] + b_map1[32 + l];
        h0 = fmaxf(h0, 0.f);
        h1 = fmaxf(h1, 0.f);
        float p0 = h0 * w_map2[l] + h1 * w_map2[32 + l];
        float p1 = h0 * w_map2[64 + l] + h1 * w_map2[96 + l];
        float p2 = h0 * w_map2[128 + l] + h1 * w_map2[160 + l];
        float p3 = h0 * w_map2[192 + l] + h1 * w_map2[224 + l];
#pragma unroll
        for (int o = 16; o > 0; o >>= 1) {
            p0 += __shfl_xor_sync(0xFFFFFFFFu, p0, o);
            p1 += __shfl_xor_sync(0xFFFFFFFFu, p1, o);
            p2 += __shfl_xor_sync(0xFFFFFFFFu, p2, o);
            p3 += __shfl_xor_sync(0xFFFFFFFFu, p3, o);
        }
        if (l == 0) {
            ((float4*)g_maps)[e] = make_float4(p0 + b_map2[0], p1 + b_map2[1],
                                               p2 + b_map2[2], p3 + b_map2[3]);
        }
    } else {
        int e = (b - 40000) * 256 + threadIdx.x;
        if (e < EE) {
            int s = src[e];
            int p = atomicAdd(&g_cursor[s], 1);
            int pos = g_rowptr[s] + p;
            g_adjdst[pos] = make_int2(e, dst[e]);
            g_pos[e] = pos;
        }
    }
}

// ---------------- K4: layer-0 gemm (313) || node_diag (79) ----------------
__global__ void __launch_bounds__(256) k4_k() {
    int b = blockIdx.x;
    if (b < 313) {
        gemm_body<128, false>(g_h, g_Weff0, nullptr, g_Ht, NN, 128, 128, b * 64, 0, 128);
        return;
    }
    int n = (b - 313) * 256 + threadIdx.x;
    if (n >= NN) return;
    float f00 = 0.f, f01 = 0.f, f11 = 0.f;
    int beg = g_rowptr[n], end = g_rowptr[n + 1];
    const float4* maps4 = (const float4*)g_maps;
    for (int i = beg; i < end; i++) {
        float4 m = maps4[g_adjdst[i].x];
        f00 += m.x * m.x + m.z * m.z;
        f01 += m.x * m.y + m.z * m.w;
        f11 += m.y * m.y + m.w * m.w;
    }
    float t = 0.5f * (f00 + f11);
    float dd = 0.5f * (f00 - f11);
    float rad = sqrtf(dd * dd + f01 * f01);
    float l1 = t - rad, l2 = t + rad;
    float s1 = rsqrtf(fmaxf(l1, EPSV));
    float s2 = rsqrtf(fmaxf(l2, EPSV));
    float c0 = 0.5f * (s1 + s2);
    float c1 = (rad > 1e-20f) ? (s2 - s1) / (2.f * rad) : 0.f;
    float D00 = c0 + c1 * dd;
    float D01 = c1 * f01;
    float D11 = c0 - c1 * dd;
    float g00 = f00 * D00 + f01 * D01, g01 = f00 * D01 + f01 * D11;
    float g10 = f01 * D00 + f11 * D01, g11 = f01 * D01 + f11 * D11;
    float dn00 = D00 * g00 + D01 * g10, dn01 = D00 * g01 + D01 * g11;
    float dn10 = D01 * g00 + D11 * g10, dn11 = D01 * g01 + D11 * g11;
    ((float4*)g_Dinv)[n] = make_float4(D00, D01, D01, D11);
    ((float4*)g_diagn)[n] = make_float4(dn00, dn01, dn10, dn11);
}

// ---------------- K5: per-edge normalized off-diagonal blocks (write CSR order) ---------
__global__ void edge_offn_k(const int* __restrict__ src, const int* __restrict__ dst) {
    int e = blockIdx.x * blockDim.x + threadIdx.x;
    if (e >= EE) return;
    int r = (e < EH) ? e + EH : e - EH;
    const float4* maps4 = (const float4*)g_maps;
    float4 me = maps4[e];
    float4 mr = maps4[r];
    float o00 = -(me.x * mr.x + me.z * mr.z);
    float o01 = -(me.x * mr.y + me.z * mr.w);
    float o10 = -(me.y * mr.x + me.w * mr.z);
    float o11 = -(me.y * mr.y + me.w * mr.w);
    float4 Ds = ((const float4*)g_Dinv)[src[e]];
    float4 Dd = ((const float4*)g_Dinv)[dst[e]];
    float t00 = Ds.x * o00 + Ds.y * o10, t01 = Ds.x * o01 + Ds.y * o11;
    float t10 = Ds.z * o00 + Ds.w * o10, t11 = Ds.z * o01 + Ds.w * o11;
    float n00 = t00 * Dd.x + t01 * Dd.z, n01 = t00 * Dd.y + t01 * Dd.w;
    float n10 = t10 * Dd.x + t11 * Dd.z, n11 = t10 * Dd.y + t11 * Dd.w;
    ((float4*)g_offn)[g_pos[e]] = make_float4(n00, n01, n10, n11);
}

// ---------------- gather-based sheaf aggregation + elu update (warp per node) -----------
__global__ void __launch_bounds__(256) aggregate_k() {
    int w = threadIdx.x >> 5, l = threadIdx.x & 31;
    int n = blockIdx.x * 8 + w;
    if (n >= NN) return;
    const float* Hn = g_Ht + (size_t)n * 128;
    float ht0a = Hn[l], ht0b = Hn[32 + l], ht1a = Hn[64 + l], ht1b = Hn[96 + l];
    float4 dn = ((const float4*)g_diagn)[n];
    float a0a = dn.x * ht0a + dn.y * ht1a;
    float a0b = dn.x * ht0b + dn.y * ht1b;
    float a1a = dn.z * ht0a + dn.w * ht1a;
    float a1b = dn.z * ht0b + dn.w * ht1b;
    int beg = g_rowptr[n], end = g_rowptr[n + 1];
    const float4* offn4 = (const float4*)g_offn;
    int i = beg;
    for (; i + 2 <= end; i += 2) {
        float4 o0 = offn4[i];
        float4 o1 = offn4[i + 1];
        int d0 = g_adjdst[i].y;
        int d1 = g_adjdst[i + 1].y;
        const float* H0 = g_Ht + (size_t)d0 * 128;
        const float* H1 = g_Ht + (size_t)d1 * 128;
        float x0a = H0[l], x0b = H0[32 + l], x1a = H0[64 + l], x1b = H0[96 + l];
        float y0a = H1[l], y0b = H1[32 + l], y1a = H1[64 + l], y1b = H1[96 + l];
        a0a += o0.x * x0a + o0.y * x1a;
        a0b += o0.x * x0b + o0.y * x1b;
        a1a += o0.z * x0a + o0.w * x1a;
        a1b += o0.z * x0b + o0.w * x1b;
        a0a += o1.x * y0a + o1.y * y1a;
        a0b += o1.x * y0b + o1.y * y1b;
        a1a += o1.z * y0a + o1.w * y1a;
        a1b += o1.z * y0b + o1.w * y1b;
    }
    for (; i < end; i++) {
        float4 o = offn4[i];
        int dd = g_adjdst[i].y;
        const float* H = g_Ht + (size_t)dd * 128;
        float x0a = H[l], x0b = H[32 + l], x1a = H[64 + l], x1b = H[96 + l];
        a0a += o.x * x0a + o.y * x1a;
        a0b += o.x * x0b + o.y * x1b;
        a1a += o.z * x0a + o.w * x1a;
        a1b += o.z * x0b + o.w * x1b;
    }
    float* h3 = g_h + (size_t)n * 128;
    h3[l] -= eluf(a0a);
    h3[32 + l] -= eluf(a0b);
    h3[64 + l] -= eluf(a1a);
    h3[96 + l] -= eluf(a1b);
}

// ---------------- plain gemm wrappers ----------------
__global__ void __launch_bounds__(256) gemm_l1_k() {
    gemm_body<128, false>(g_h, g_Weff1, nullptr, g_Ht, NN, 128, 128, blockIdx.x * 64, 0,
                          128);
}
__global__ void __launch_bounds__(256) gemm_out1_k(const float* __restrict__ w_out1,
                                                   const float* __restrict__ b_out1) {
    gemm_body<64, true>(g_h, w_out1, b_out1, g_h1, NN, 64, 128, blockIdx.x * 64, 0, 64);
}
__global__ void __launch_bounds__(256) gemm_out2_k(const float* __restrict__ w_out2,
                                                   const float* __restrict__ b_out2,
                                                   float* __restrict__ out) {
    gemm_body<64, false>(g_h1, w_out2, b_out2, out, NN, 40, 64, blockIdx.x * 64, 0, 40);
}

// ---------------- host ----------------
extern "C" void kernel_launch(void* const* d_in, const int* in_sizes, int n_in,
                              void* d_out, int out_size) {
    (void)in_sizes; (void)n_in; (void)out_size;
    const float* x = (const float*)d_in[0];
    const int* ei = (const int*)d_in[1];
    const int* src = ei;
    const int* dst = ei + EE;
    const float* w_in1 = (const float*)d_in[2];
    const float* b_in1 = (const float*)d_in[3];
    const float* w_in2 = (const float*)d_in[4];
    const float* b_in2 = (const float*)d_in[5];
    const float* w_map1 = (const float*)d_in[6];
    const float* b_map1 = (const float*)d_in[7];
    const float* w_map2 = (const float*)d_in[8];
    const float* b_map2 = (const float*)d_in[9];
    const float* w_out1 = (const float*)d_in[10];
    const float* b_out1 = (const float*)d_in[11];
    const float* w_out2 = (const float*)d_in[12];
    const float* b_out2 = (const float*)d_in[13];
    const float* W1_0 = (const float*)d_in[14];
    const float* W2_0 = (const float*)d_in[15];
    const float* W1_1 = (const float*)d_in[16];
    const float* W2_1 = (const float*)d_in[17];
    float* out = (float*)d_out;

    prep_k<<<79, 256>>>(w_map1, W1_0, W2_0, W1_1, W2_1);
    k1_k<<<313 + 1250 + 32, 256>>>(x, w_in1, b_in1, src, w_in2, b_in2);
    k2_k<<<626 + 1, 256>>>(b_in2);
    k3_k<<<40000 + 1250, 256>>>(src, dst, b_map1, w_map2, b_map2);
    k4_k<<<313 + 79, 256>>>();
    edge_offn_k<<<1250, 256>>>(src, dst);
    aggregate_k<<<2500, 256>>>();
    gemm_l1_k<<<313, 256>>>();
    aggregate_k<<<2500, 256>>>();
    gemm_out1_k<<<313, 256>>>(w_out1, b_out1);
    gemm_out2_k<<<313, 256>>>(w_out2, b_out2, out);
}

// round 7
// speedup vs baseline: 1.6490x; 1.0642x over previous
#include <cuda_runtime.h>
#include <cuda_bf16.h>
#include <math.h>
#include <stdint.h>

#define NN 20000
#define EE 320000
#define EH 160000
#define EPSV 1e-6f

// ---------------- scratch (static device globals; no allocs) ----------------
__device__ float g_h1[NN * 64];
__device__ float g_h[NN * 128];
__device__ float g_P[NN * 128];
__device__ float g_Wab[128 * 128];
__device__ float g_Wc[256 * 64];       // [w_in2 ; Wab@w_in2]
__device__ float g_bP[128];            // Wab @ b_in2
__device__ float g_Weff0[128 * 128];
__device__ float g_Weff1[128 * 128];
__device__ float g_maps[EE * 4];
__device__ float g_Dinv[NN * 4];
__device__ float g_diagn[NN * 4];
__device__ float g_offn[EE * 4];       // CSR order
__device__ float g_Ht[NN * 128];
__device__ int g_deg[NN];
__device__ int g_cursor[NN];
__device__ int g_rowptr[NN + 1];
__device__ int2 g_adjdst[EE];          // CSR slot -> (edge id, dst node)
__device__ int g_pos[EE];              // edge id -> CSR slot

__device__ __forceinline__ float eluf(float v) {
    return v > 0.f ? v : (expf(v) - 1.f);
}

__device__ __forceinline__ uint32_t packbf(__nv_bfloat16 a, __nv_bfloat16 b) {
    __nv_bfloat162 t = __halves2bfloat162(a, b);
    return *reinterpret_cast<uint32_t*>(&t);
}

#define MMA16816(c, a, b0_, b1_)                                             \
    asm volatile(                                                            \
        "mma.sync.aligned.m16n8k16.row.col.f32.bf16.bf16.f32 "               \
        "{%0,%1,%2,%3}, {%4,%5,%6,%7}, {%8,%9}, {%0,%1,%2,%3};"              \
        : "+f"((c)[0]), "+f"((c)[1]), "+f"((c)[2]), "+f"((c)[3])             \
        : "r"((a)[0]), "r"((a)[1]), "r"((a)[2]), "r"((a)[3]),                \
          "r"(b0_), "r"(b1_))

// ---------------- tensor-core GEMM body ----------------
template <int BN, bool RELU>
__device__ __forceinline__ void gemm_body(const float* __restrict__ A,
                                          const float* __restrict__ W,
                                          const float* __restrict__ bias,
                                          float* __restrict__ C,
                                          int M, int N, int K, int bm, int bn, int ldc) {
    constexpr int BM = 64;
    constexpr int WN = BN / 4;
    constexpr int NSUB = WN / 8;
    constexpr int SW = 12;

    __shared__ uint32_t sAh[BM * SW], sAl[BM * SW];
    __shared__ uint32_t sWh[BN * SW], sWl[BN * SW];

    const int tid = threadIdx.x;
    const int lane = tid & 31;
    const int wid = tid >> 5;
    const int warp_m = wid & 1;
    const int warp_n = wid >> 1;
    const int qr = lane >> 2;
    const int qc = lane & 3;

    const int lm = tid >> 2;
    const int lk = (tid & 3) * 4;
    const int wof = lk >> 1;

    float acc[2][NSUB][4];
#pragma unroll
    for (int i = 0; i < 2; i++)
#pragma unroll
        for (int j = 0; j < NSUB; j++)
#pragma unroll
            for (int q = 0; q < 4; q++) acc[i][j][q] = 0.f;

    float4 a_reg;
    float4 w_reg[BN / 64];

    auto loadA = [&](int k0) {
        int m = bm + lm;
        a_reg = (m < M) ? *(const float4*)(A + (size_t)m * K + k0 + lk)
                        : make_float4(0.f, 0.f, 0.f, 0.f);
    };
    auto loadW = [&](int k0) {
#pragma unroll
        for (int i = 0; i < BN / 64; i++) {
            int n = bn + lm + i * 64;
            w_reg[i] = (n < N) ? *(const float4*)(W + (size_t)n * K + k0 + lk)
                               : make_float4(0.f, 0.f, 0.f, 0.f);
        }
    };

    auto storeSplit = [&](uint32_t* hi, uint32_t* lo, int row, float4 v) {
        __nv_bfloat16 h0 = __float2bfloat16(v.x), h1 = __float2bfloat16(v.y);
        __nv_bfloat16 h2 = __float2bfloat16(v.z), h3 = __float2bfloat16(v.w);
        __nv_bfloat16 l0 = __float2bfloat16(v.x - __bfloat162float(h0));
        __nv_bfloat16 l1 = __float2bfloat16(v.y - __bfloat162float(h1));
        __nv_bfloat16 l2 = __float2bfloat16(v.z - __bfloat162float(h2));
        __nv_bfloat16 l3 = __float2bfloat16(v.w - __bfloat162float(h3));
        int w0 = row * SW + wof;
        hi[w0 + 0] = packbf(h0, h1);
        hi[w0 + 1] = packbf(h2, h3);
        lo[w0 + 0] = packbf(l0, l1);
        lo[w0 + 1] = packbf(l2, l3);
    };

    loadA(0);
    loadW(0);

    for (int k0 = 0; k0 < K; k0 += 16) {
        storeSplit(sAh, sAl, lm, a_reg);
#pragma unroll
        for (int i = 0; i < BN / 64; i++) storeSplit(sWh, sWl, lm + i * 64, w_reg[i]);
        __syncthreads();

        if (k0 + 16 < K) {
            loadA(k0 + 16);
            loadW(k0 + 16);
        }

        uint32_t ah[2][4], al[2][4];
#pragma unroll
        for (int ms = 0; ms < 2; ms++) {
            int r = warp_m * 32 + ms * 16 + qr;
            int b0 = r * SW + qc;
            ah[ms][0] = sAh[b0];
            ah[ms][1] = sAh[b0 + 8 * SW];
            ah[ms][2] = sAh[b0 + 4];
            ah[ms][3] = sAh[b0 + 8 * SW + 4];
            al[ms][0] = sAl[b0];
            al[ms][1] = sAl[b0 + 8 * SW];
            al[ms][2] = sAl[b0 + 4];
            al[ms][3] = sAl[b0 + 8 * SW + 4];
        }

#pragma unroll
        for (int ns = 0; ns < NSUB; ns++) {
            int n = warp_n * WN + ns * 8 + qr;
            int b = n * SW + qc;
            uint32_t bh0 = sWh[b], bh1 = sWh[b + 4];
            uint32_t bl0 = sWl[b], bl1 = sWl[b + 4];
#pragma unroll
            for (int ms = 0; ms < 2; ms++) {
                MMA16816(acc[ms][ns], ah[ms], bh0, bh1);
                MMA16816(acc[ms][ns], ah[ms], bl0, bl1);
                MMA16816(acc[ms][ns], al[ms], bh0, bh1);
            }
        }
        __syncthreads();
    }

#pragma unroll
    for (int ms = 0; ms < 2; ms++) {
#pragma unroll
        for (int ns = 0; ns < NSUB; ns++) {
            int m0 = bm + warp_m * 32 + ms * 16 + qr;
            int n0 = bn + warp_n * WN + ns * 8 + 2 * qc;
            const float* c = acc[ms][ns];
#pragma unroll
            for (int half = 0; half < 2; half++) {
                int m = m0 + half * 8;
                if (m >= M) continue;
                float v0 = c[half * 2 + 0];
                float v1 = c[half * 2 + 1];
                if (n0 + 1 < N) {
                    v0 += bias ? bias[n0] : 0.f;
                    v1 += bias ? bias[n0 + 1] : 0.f;
                    if (RELU) { v0 = fmaxf(v0, 0.f); v1 = fmaxf(v1, 0.f); }
                    *(float2*)(C + (size_t)m * ldc + n0) = make_float2(v0, v1);
                } else if (n0 < N) {
                    v0 += bias ? bias[n0] : 0.f;
                    if (RELU) v0 = fmaxf(v0, 0.f);
                    C[(size_t)m * ldc + n0] = v0;
                }
            }
        }
    }
}

// ---------------- prep ----------------
__global__ void prep_k(const float* __restrict__ w_map1,
                       const float* __restrict__ W1_0, const float* __restrict__ W2_0,
                       const float* __restrict__ W1_1, const float* __restrict__ W2_1) {
    int i = blockIdx.x * blockDim.x + threadIdx.x;
    if (i < 128 * 128) {
        int j = i >> 7, k = i & 127;
        g_Wab[i] = (j < 64) ? w_map1[j * 256 + k] : w_map1[(j - 64) * 256 + 128 + k];
        int r = i >> 7, c = i & 127;
        int ii = r >> 6, g = r & 63;
        int jj = c >> 6, f = c & 63;
        g_Weff0[i] = W1_0[jj * 2 + ii] * W2_0[g * 64 + f];
        g_Weff1[i] = W1_1[jj * 2 + ii] * W2_1[g * 64 + f];
    }
    if (i < NN) {
        g_deg[i] = 0;
        g_cursor[i] = 0;
    }
}

// ---------------- K1: input-MLP gemm || hist || weight combine ----------------
__global__ void __launch_bounds__(256) k1_k(const float* __restrict__ x,
                                            const float* __restrict__ w_in1,
                                            const float* __restrict__ b_in1,
                                            const int* __restrict__ src,
                                            const float* __restrict__ w_in2,
                                            const float* __restrict__ b_in2) {
    int b = blockIdx.x;
    if (b < 313) {
        gemm_body<64, true>(x, w_in1, b_in1, g_h1, NN, 64, 512, b * 64, 0, 64);
    } else if (b < 1563) {
        int e = (b - 313) * 256 + threadIdx.x;
        if (e < EE) atomicAdd(&g_deg[src[e]], 1);
    } else {
        int g = (b - 1563) * 256 + threadIdx.x;  // 0..8191
        g_Wc[g] = w_in2[g];
        int i = g >> 6, k = g & 63;
        float s = 0.f;
#pragma unroll 4
        for (int j = 0; j < 128; j++) s += g_Wab[i * 128 + j] * w_in2[j * 64 + k];
        g_Wc[8192 + g] = s;
        if (g < 128) {
            float sb = 0.f;
            for (int j = 0; j < 128; j++) sb += g_Wab[g * 128 + j] * b_in2[j];
            g_bP[g] = sb;
        }
    }
}

// ---------------- scan body ----------------
__device__ void scan_body() {
    __shared__ int wsum[8];
    __shared__ int carry;
    int t = threadIdx.x, l = t & 31, w = t >> 5;
    if (t == 0) { carry = 0; g_rowptr[0] = 0; }
    __syncthreads();
    for (int base = 0; base < NN; base += 256) {
        int v = (base + t < NN) ? g_deg[base + t] : 0;
        int x = v;
#pragma unroll
        for (int o = 1; o < 32; o <<= 1) {
            int y = __shfl_up_sync(0xFFFFFFFFu, x, o);
            if (l >= o) x += y;
        }
        if (l == 31) wsum[w] = x;
        __syncthreads();
        if (w == 0 && l < 8) {
            int y = wsum[l];
#pragma unroll
            for (int o = 1; o < 8; o <<= 1) {
                int z = __shfl_up_sync(0xFFu, y, o);
                if (l >= o) y += z;
            }
            wsum[l] = y;
        }
        __syncthreads();
        int off = carry + (w > 0 ? wsum[w - 1] : 0);
        if (base + t < NN) g_rowptr[base + t + 1] = off + x;
        __syncthreads();
        if (t == 0) carry += wsum[7];
        __syncthreads();
    }
}

// ---------------- K2: fused h+P gemm || scan ----------------
__global__ void __launch_bounds__(256) k2_k(const float* __restrict__ b_in2) {
    int b = blockIdx.x;
    if (b < 626) {
        int bm = (b >> 1) * 64;
        int bn = (b & 1) * 128;
        if (bn == 0) {
            gemm_body<128, false>(g_h1, g_Wc, b_in2, g_h, NN, 256, 64, bm, 0, 128);
        } else {
            gemm_body<128, false>(g_h1, g_Wc, g_bP - 128, g_P - 128, NN, 256, 64, bm, 128,
                                  128);
        }
    } else {
        scan_body();
    }
}

// ---------------- K3: edge maps (4 edges/warp, 8 lanes/edge) || scatter -----------------
// 10000 edge blocks (32 edges each) + 1250 scatter blocks.
__global__ void __launch_bounds__(256) k3_k(const int* __restrict__ src,
                                            const int* __restrict__ dst,
                                            const float* __restrict__ b_map1,
                                            const float* __restrict__ w_map2,
                                            const float* __restrict__ b_map2) {
    int b = blockIdx.x;
    if (b < 10000) {
        const int lane = threadIdx.x & 31;
        const int wrp = threadIdx.x >> 5;
        const int g = lane >> 3;   // edge within warp group (0..3)
        const int c = lane & 7;    // channel octet (0..7)
        const int e = b * 32 + wrp * 4 + g;

        // per-lane fixed weights / bias (registers, loaded once)
        const int ch = c * 8;
        float4 w0[4], w1[4];
#pragma unroll
        for (int o = 0; o < 4; o++) {
            w0[o] = *(const float4*)(w_map2 + o * 64 + ch);
            w1[o] = *(const float4*)(w_map2 + o * 64 + ch + 4);
        }
        float4 bb0 = *(const float4*)(b_map1 + ch);
        float4 bb1 = *(const float4*)(b_map1 + ch + 4);

        int s = src[e], d = dst[e];
        const float* As = g_P + (size_t)s * 128 + ch;
        const float* Bd = g_P + (size_t)d * 128 + 64 + ch;
        float4 a0 = *(const float4*)(As);
        float4 a1 = *(const float4*)(As + 4);
        float4 v0 = *(const float4*)(Bd);
        float4 v1 = *(const float4*)(Bd + 4);

        float h[8];
        h[0] = fmaxf(a0.x + v0.x + bb0.x, 0.f);
        h[1] = fmaxf(a0.y + v0.y + bb0.y, 0.f);
        h[2] = fmaxf(a0.z + v0.z + bb0.z, 0.f);
        h[3] = fmaxf(a0.w + v0.w + bb0.w, 0.f);
        h[4] = fmaxf(a1.x + v1.x + bb1.x, 0.f);
        h[5] = fmaxf(a1.y + v1.y + bb1.y, 0.f);
        h[6] = fmaxf(a1.z + v1.z + bb1.z, 0.f);
        h[7] = fmaxf(a1.w + v1.w + bb1.w, 0.f);

        float p[4];
#pragma unroll
        for (int o = 0; o < 4; o++) {
            p[o] = h[0] * w0[o].x + h[1] * w0[o].y + h[2] * w0[o].z + h[3] * w0[o].w +
                   h[4] * w1[o].x + h[5] * w1[o].y + h[6] * w1[o].z + h[7] * w1[o].w;
        }
        // reduce across the 8-lane group (xor 1,2,4 stay within group)
#pragma unroll
        for (int o = 0; o < 4; o++) {
            p[o] += __shfl_xor_sync(0xFFFFFFFFu, p[o], 1);
            p[o] += __shfl_xor_sync(0xFFFFFFFFu, p[o], 2);
            p[o] += __shfl_xor_sync(0xFFFFFFFFu, p[o], 4);
        }
        if (c == 0) {
            ((float4*)g_maps)[e] = make_float4(p[0] + b_map2[0], p[1] + b_map2[1],
                                               p[2] + b_map2[2], p[3] + b_map2[3]);
        }
    } else {
        int e = (b - 10000) * 256 + threadIdx.x;
        if (e < EE) {
            int s = src[e];
            int p = atomicAdd(&g_cursor[s], 1);
            int pos = g_rowptr[s] + p;
            g_adjdst[pos] = make_int2(e, dst[e]);
            g_pos[e] = pos;
        }
    }
}

// ---------------- K4: layer-0 gemm (313) || node_diag (79) ----------------
__global__ void __launch_bounds__(256) k4_k() {
    int b = blockIdx.x;
    if (b < 313) {
        gemm_body<128, false>(g_h, g_Weff0, nullptr, g_Ht, NN, 128, 128, b * 64, 0, 128);
        return;
    }
    int n = (b - 313) * 256 + threadIdx.x;
    if (n >= NN) return;
    float f00 = 0.f, f01 = 0.f, f11 = 0.f;
    int beg = g_rowptr[n], end = g_rowptr[n + 1];
    const float4* maps4 = (const float4*)g_maps;
    for (int i = beg; i < end; i++) {
        float4 m = maps4[g_adjdst[i].x];
        f00 += m.x * m.x + m.z * m.z;
        f01 += m.x * m.y + m.z * m.w;
        f11 += m.y * m.y + m.w * m.w;
    }
    float t = 0.5f * (f00 + f11);
    float dd = 0.5f * (f00 - f11);
    float rad = sqrtf(dd * dd + f01 * f01);
    float l1 = t - rad, l2 = t + rad;
    float s1 = rsqrtf(fmaxf(l1, EPSV));
    float s2 = rsqrtf(fmaxf(l2, EPSV));
    float c0 = 0.5f * (s1 + s2);
    float c1 = (rad > 1e-20f) ? (s2 - s1) / (2.f * rad) : 0.f;
    float D00 = c0 + c1 * dd;
    float D01 = c1 * f01;
    float D11 = c0 - c1 * dd;
    float g00 = f00 * D00 + f01 * D01, g01 = f00 * D01 + f01 * D11;
    float g10 = f01 * D00 + f11 * D01, g11 = f01 * D01 + f11 * D11;
    float dn00 = D00 * g00 + D01 * g10, dn01 = D00 * g01 + D01 * g11;
    float dn10 = D01 * g00 + D11 * g10, dn11 = D01 * g01 + D11 * g11;
    ((float4*)g_Dinv)[n] = make_float4(D00, D01, D01, D11);
    ((float4*)g_diagn)[n] = make_float4(dn00, dn01, dn10, dn11);
}

// ---------------- per-edge normalized off-diagonal blocks (write CSR order) -------------
__global__ void edge_offn_k(const int* __restrict__ src, const int* __restrict__ dst) {
    int e = blockIdx.x * blockDim.x + threadIdx.x;
    if (e >= EE) return;
    int r = (e < EH) ? e + EH : e - EH;
    const float4* maps4 = (const float4*)g_maps;
    float4 me = maps4[e];
    float4 mr = maps4[r];
    float o00 = -(me.x * mr.x + me.z * mr.z);
    float o01 = -(me.x * mr.y + me.z * mr.w);
    float o10 = -(me.y * mr.x + me.w * mr.z);
    float o11 = -(me.y * mr.y + me.w * mr.w);
    float4 Ds = ((const float4*)g_Dinv)[src[e]];
    float4 Dd = ((const float4*)g_Dinv)[dst[e]];
    float t00 = Ds.x * o00 + Ds.y * o10, t01 = Ds.x * o01 + Ds.y * o11;
    float t10 = Ds.z * o00 + Ds.w * o10, t11 = Ds.z * o01 + Ds.w * o11;
    float n00 = t00 * Dd.x + t01 * Dd.z, n01 = t00 * Dd.y + t01 * Dd.w;
    float n10 = t10 * Dd.x + t11 * Dd.z, n11 = t10 * Dd.y + t11 * Dd.w;
    ((float4*)g_offn)[g_pos[e]] = make_float4(n00, n01, n10, n11);
}

// ---------------- gather-based sheaf aggregation + elu update (warp per node) -----------
__global__ void __launch_bounds__(256) aggregate_k() {
    int w = threadIdx.x >> 5, l = threadIdx.x & 31;
    int n = blockIdx.x * 8 + w;
    if (n >= NN) return;
    const float* Hn = g_Ht + (size_t)n * 128;
    float ht0a = Hn[l], ht0b = Hn[32 + l], ht1a = Hn[64 + l], ht1b = Hn[96 + l];
    float4 dn = ((const float4*)g_diagn)[n];
    float a0a = dn.x * ht0a + dn.y * ht1a;
    float a0b = dn.x * ht0b + dn.y * ht1b;
    float a1a = dn.z * ht0a + dn.w * ht1a;
    float a1b = dn.z * ht0b + dn.w * ht1b;
    int beg = g_rowptr[n], end = g_rowptr[n + 1];
    const float4* offn4 = (const float4*)g_offn;
    int i = beg;
    for (; i + 2 <= end; i += 2) {
        float4 o0 = offn4[i];
        float4 o1 = offn4[i + 1];
        int d0 = g_adjdst[i].y;
        int d1 = g_adjdst[i + 1].y;
        const float* H0 = g_Ht + (size_t)d0 * 128;
        const float* H1 = g_Ht + (size_t)d1 * 128;
        float x0a = H0[l], x0b = H0[32 + l], x1a = H0[64 + l], x1b = H0[96 + l];
        float y0a = H1[l], y0b = H1[32 + l], y1a = H1[64 + l], y1b = H1[96 + l];
        a0a += o0.x * x0a + o0.y * x1a;
        a0b += o0.x * x0b + o0.y * x1b;
        a1a += o0.z * x0a + o0.w * x1a;
        a1b += o0.z * x0b + o0.w * x1b;
        a0a += o1.x * y0a + o1.y * y1a;
        a0b += o1.x * y0b + o1.y * y1b;
        a1a += o1.z * y0a + o1.w * y1a;
        a1b += o1.z * y0b + o1.w * y1b;
    }
    for (; i < end; i++) {
        float4 o = offn4[i];
        int dd = g_adjdst[i].y;
        const float* H = g_Ht + (size_t)dd * 128;
        float x0a = H[l], x0b = H[32 + l], x1a = H[64 + l], x1b = H[96 + l];
        a0a += o.x * x0a + o.y * x1a;
        a0b += o.x * x0b + o.y * x1b;
        a1a += o.z * x0a + o.w * x1a;
        a1b += o.z * x0b + o.w * x1b;
    }
    float* h3 = g_h + (size_t)n * 128;
    h3[l] -= eluf(a0a);
    h3[32 + l] -= eluf(a0b);
    h3[64 + l] -= eluf(a1a);
    h3[96 + l] -= eluf(a1b);
}

// ---------------- plain gemm wrappers ----------------
__global__ void __launch_bounds__(256) gemm_l1_k() {
    gemm_body<128, false>(g_h, g_Weff1, nullptr, g_Ht, NN, 128, 128, blockIdx.x * 64, 0,
                          128);
}
__global__ void __launch_bounds__(256) gemm_out1_k(const float* __restrict__ w_out1,
                                                   const float* __restrict__ b_out1) {
    gemm_body<64, true>(g_h, w_out1, b_out1, g_h1, NN, 64, 128, blockIdx.x * 64, 0, 64);
}
__global__ void __launch_bounds__(256) gemm_out2_k(const float* __restrict__ w_out2,
                                                   const float* __restrict__ b_out2,
                                                   float* __restrict__ out) {
    gemm_body<64, false>(g_h1, w_out2, b_out2, out, NN, 40, 64, blockIdx.x * 64, 0, 40);
}

// ---------------- host ----------------
extern "C" void kernel_launch(void* const* d_in, const int* in_sizes, int n_in,
                              void* d_out, int out_size) {
    (void)in_sizes; (void)n_in; (void)out_size;
    const float* x = (const float*)d_in[0];
    const int* ei = (const int*)d_in[1];
    const int* src = ei;
    const int* dst = ei + EE;
    const float* w_in1 = (const float*)d_in[2];
    const float* b_in1 = (const float*)d_in[3];
    const float* w_in2 = (const float*)d_in[4];
    const float* b_in2 = (const float*)d_in[5];
    const float* w_map1 = (const float*)d_in[6];
    const float* b_map1 = (const float*)d_in[7];
    const float* w_map2 = (const float*)d_in[8];
    const float* b_map2 = (const float*)d_in[9];
    const float* w_out1 = (const float*)d_in[10];
    const float* b_out1 = (const float*)d_in[11];
    const float* w_out2 = (const float*)d_in[12];
    const float* b_out2 = (const float*)d_in[13];
    const float* W1_0 = (const float*)d_in[14];
    const float* W2_0 = (const float*)d_in[15];
    const float* W1_1 = (const float*)d_in[16];
    const float* W2_1 = (const float*)d_in[17];
    float* out = (float*)d_out;

    prep_k<<<79, 256>>>(w_map1, W1_0, W2_0, W1_1, W2_1);
    k1_k<<<313 + 1250 + 32, 256>>>(x, w_in1, b_in1, src, w_in2, b_in2);
    k2_k<<<626 + 1, 256>>>(b_in2);
    k3_k<<<10000 + 1250, 256>>>(src, dst, b_map1, w_map2, b_map2);
    k4_k<<<313 + 79, 256>>>();
    edge_offn_k<<<1250, 256>>>(src, dst);
    aggregate_k<<<2500, 256>>>();
    gemm_l1_k<<<313, 256>>>();
    aggregate_k<<<2500, 256>>>();
    gemm_out1_k<<<313, 256>>>(w_out1, b_out1);
    gemm_out2_k<<<313, 256>>>(w_out2, b_out2, out);
}